// round 1
// baseline (speedup 1.0000x reference)
#include <cuda_runtime.h>
#include <math.h>

// Problem constants (fixed shapes)
#define BATCH 2
#define LSEQ 256
#define CB 64
#define DMODEL 512
#define NHEAD 8
#define HD 64
#define NROWS (BATCH*LSEQ)   // 512
#define PSTR 68              // padded pair row stride (floats): conflict-free for f4

// Static scratch (no allocations allowed)
__device__ float g_Q[NROWS*DMODEL];
__device__ float g_qk[NROWS*DMODEL];   // [row][h][c]
__device__ float g_qb[NROWS*NHEAD];
__device__ float g_ctx[NROWS*DMODEL];
__device__ float g_o[NROWS*DMODEL];

// ---------------------------------------------------------------------------
// GEMM: C[M=512,N=512] = A[512,512] @ W[512,512] + bias[512]
// BM=32, BN=64, BK=32; grid (8,16), 256 threads; 2x4 outputs/thread.
// ---------------------------------------------------------------------------
__global__ __launch_bounds__(256) void gemm_bias_kernel(
    const float* __restrict__ A, const float* __restrict__ W,
    const float* __restrict__ bias, float* __restrict__ C)
{
    __shared__ float As[32][33];
    __shared__ float Bs[32][68];
    const int bx = blockIdx.x;   // col tile (BN=64)
    const int by = blockIdx.y;   // row tile (BM=32)
    const int tid = threadIdx.x;
    const int tx = tid & 15;     // col group (4 cols)
    const int ty = tid >> 4;     // row group (2 rows)
    const int col0 = bx*64 + tx*4;
    const int row0 = by*32 + ty*2;

    float acc[2][4] = {};

    for (int kb = 0; kb < DMODEL; kb += 32) {
        // A tile: 32x32 floats = 256 float4, one per thread
        {
            int r  = tid >> 3;
            int k4 = tid & 7;
            float4 v = *(const float4*)&A[(by*32 + r)*DMODEL + kb + k4*4];
            As[r][k4*4+0] = v.x; As[r][k4*4+1] = v.y;
            As[r][k4*4+2] = v.z; As[r][k4*4+3] = v.w;
        }
        // B tile: 32x64 floats = 512 float4, two per thread
        #pragma unroll
        for (int p = 0; p < 2; p++) {
            int f  = tid + p*256;
            int k  = f >> 4;
            int n4 = f & 15;
            float4 v = *(const float4*)&W[(kb + k)*DMODEL + bx*64 + n4*4];
            *(float4*)&Bs[k][n4*4] = v;
        }
        __syncthreads();
        #pragma unroll
        for (int k = 0; k < 32; k++) {
            float a0 = As[ty*2+0][k];
            float a1 = As[ty*2+1][k];
            float4 b = *(const float4*)&Bs[k][tx*4];
            acc[0][0] += a0*b.x; acc[0][1] += a0*b.y; acc[0][2] += a0*b.z; acc[0][3] += a0*b.w;
            acc[1][0] += a1*b.x; acc[1][1] += a1*b.y; acc[1][2] += a1*b.z; acc[1][3] += a1*b.w;
        }
        __syncthreads();
    }
    float4 bb = *(const float4*)&bias[col0];
    #pragma unroll
    for (int rr = 0; rr < 2; rr++) {
        float4 o;
        o.x = acc[rr][0] + bb.x; o.y = acc[rr][1] + bb.y;
        o.z = acc[rr][2] + bb.z; o.w = acc[rr][3] + bb.w;
        *(float4*)&C[(row0+rr)*DMODEL + col0] = o;
    }
}

// ---------------------------------------------------------------------------
// qk[row][h][c] = (1/8) * sum_d Q[row][h*64+d] * Wk[c][h*64+d]
// qb[row][h]    = (1/8) * sum_d Q[row][h*64+d] * bk[h*64+d]
// 512 blocks (one per row), 256 threads.
// ---------------------------------------------------------------------------
__global__ __launch_bounds__(256) void qk_kernel(
    const float* __restrict__ Wk, const float* __restrict__ bk)
{
    __shared__ float Qrow[DMODEL];
    const int row = blockIdx.x;
    const int tid = threadIdx.x;
    *(float2*)&Qrow[tid*2] = *(const float2*)&g_Q[row*DMODEL + tid*2];
    __syncthreads();

    #pragma unroll
    for (int p = 0; p < 2; p++) {
        int idx = tid + p*256;
        int h = idx >> 6, c = idx & 63;
        const float* wrow = &Wk[c*DMODEL + h*64];
        const float* q    = &Qrow[h*64];
        float acc = 0.f;
        #pragma unroll
        for (int d4 = 0; d4 < 16; d4++) {
            float4 qv = *(const float4*)&q[d4*4];
            float4 wv = *(const float4*)&wrow[d4*4];
            acc += qv.x*wv.x + qv.y*wv.y + qv.z*wv.z + qv.w*wv.w;
        }
        g_qk[row*DMODEL + idx] = acc * 0.125f;
    }
    if (tid < NHEAD) {
        float acc = 0.f;
        #pragma unroll
        for (int d = 0; d < HD; d++) acc += Qrow[tid*64 + d] * bk[tid*64 + d];
        g_qb[row*NHEAD + tid] = acc * 0.125f;
    }
}

// ---------------------------------------------------------------------------
// Attention per (b,i): one block per row. 256 threads (thread = key index j).
//   scores[h][j] = pair_row[j,:] . qk[row][h][:] + qb[row][h]     (scale folded)
//   softmax over j, wp[h][c] = sum_j w[h][j]*pair_row[j][c]
//   ctx[row][h*64+d] = sum_c wp[h][c]*Wv[c][h*64+d] + bv[h*64+d]
// ---------------------------------------------------------------------------
__global__ __launch_bounds__(256) void attn_kernel(
    const float* __restrict__ pair, const float* __restrict__ Wv,
    const float* __restrict__ bv)
{
    extern __shared__ float sm[];
    float* pairS = sm;                       // 256*68
    float* qk_sm = sm + 256*PSTR;            // 512
    float* qb_sm = qk_sm + DMODEL;           // 8
    float* w_sm  = qb_sm + 8;                // 8*256
    float* wp_sm = w_sm + NHEAD*LSEQ;        // 512
    float* red   = wp_sm + DMODEL;           // 64

    const int row  = blockIdx.x;
    const int tid  = threadIdx.x;
    const int lane = tid & 31;
    const int warp = tid >> 5;

    // Load pair row tile (256 x 64) into padded SMEM
    const float4* pg = (const float4*)(pair + (size_t)row * (LSEQ*CB));
    #pragma unroll
    for (int it = 0; it < 16; it++) {
        int f  = tid + it*256;
        int j  = f >> 4;
        int c4 = f & 15;
        float4 v = pg[f];
        *(float4*)&pairS[j*PSTR + c4*4] = v;
    }
    *(float2*)&qk_sm[tid*2] = *(const float2*)&g_qk[row*DMODEL + tid*2];
    if (tid < NHEAD) qb_sm[tid] = g_qb[row*NHEAD + tid];
    __syncthreads();

    // Scores for this thread's j across all heads
    float s[NHEAD];
    #pragma unroll
    for (int h = 0; h < NHEAD; h++) s[h] = qb_sm[h];
    const float4* prow = (const float4*)&pairS[tid*PSTR];
    #pragma unroll
    for (int c4 = 0; c4 < 16; c4++) {
        float4 p = prow[c4];
        #pragma unroll
        for (int h = 0; h < NHEAD; h++) {
            float4 q = *(const float4*)&qk_sm[h*64 + c4*4];
            s[h] += p.x*q.x + p.y*q.y + p.z*q.z + p.w*q.w;
        }
    }

    // Block softmax over j (per head): max
    #pragma unroll
    for (int h = 0; h < NHEAD; h++) {
        float v = s[h];
        #pragma unroll
        for (int o = 16; o; o >>= 1) v = fmaxf(v, __shfl_xor_sync(0xffffffffu, v, o));
        if (lane == 0) red[warp*NHEAD + h] = v;
    }
    __syncthreads();
    float m[NHEAD];
    #pragma unroll
    for (int h = 0; h < NHEAD; h++) {
        float v = red[h];
        #pragma unroll
        for (int w2 = 1; w2 < 8; w2++) v = fmaxf(v, red[w2*NHEAD + h]);
        m[h] = v;
    }
    __syncthreads();   // before reusing red

    // exp + sum
    float e[NHEAD], Zi[NHEAD];
    #pragma unroll
    for (int h = 0; h < NHEAD; h++) {
        e[h] = expf(s[h] - m[h]);
        float v = e[h];
        #pragma unroll
        for (int o = 16; o; o >>= 1) v += __shfl_xor_sync(0xffffffffu, v, o);
        if (lane == 0) red[warp*NHEAD + h] = v;
    }
    __syncthreads();
    #pragma unroll
    for (int h = 0; h < NHEAD; h++) {
        float v = 0.f;
        #pragma unroll
        for (int w2 = 0; w2 < 8; w2++) v += red[w2*NHEAD + h];
        Zi[h] = 1.0f / v;
        w_sm[h*LSEQ + tid] = e[h];
    }
    __syncthreads();

    // wp[h][c] = (sum_j e[h][j]*pair[j][c]) * Zi[h]  -> 512 outputs, 2/thread
    #pragma unroll
    for (int p = 0; p < 2; p++) {
        int idx = tid + p*256;
        int h = idx >> 6, c = idx & 63;
        float acc = 0.f;
        #pragma unroll 8
        for (int j4 = 0; j4 < 64; j4++) {
            float4 wv = *(const float4*)&w_sm[h*LSEQ + j4*4];
            acc += wv.x * pairS[(j4*4+0)*PSTR + c]
                 + wv.y * pairS[(j4*4+1)*PSTR + c]
                 + wv.z * pairS[(j4*4+2)*PSTR + c]
                 + wv.w * pairS[(j4*4+3)*PSTR + c];
        }
        wp_sm[idx] = acc * Zi[h];
    }
    __syncthreads();

    // ctx[row][h*64+d] = sum_c wp[h][c]*Wv[c][h*64+d] + bv
    #pragma unroll
    for (int p = 0; p < 2; p++) {
        int idx = tid + p*256;
        int h = idx >> 6, d = idx & 63;
        float acc = bv[idx];
        const float* wvp = &Wv[h*64 + d];
        const float* wpp = &wp_sm[h*64];
        #pragma unroll 16
        for (int c = 0; c < 64; c++) acc += wpp[c] * wvp[c*DMODEL];
        g_ctx[row*DMODEL + idx] = acc;
    }
}

// ---------------------------------------------------------------------------
// LayerNorm(o + x) * gamma + beta -> out. 512 blocks x 128 threads (4 elems).
// ---------------------------------------------------------------------------
__global__ __launch_bounds__(128) void ln_kernel(
    const float* __restrict__ x, const float* __restrict__ gamma,
    const float* __restrict__ beta, float* __restrict__ out)
{
    __shared__ float rs[8];
    const int row = blockIdx.x;
    const int tid = threadIdx.x;
    const int lane = tid & 31, warp = tid >> 5;

    float4 o4 = *(const float4*)&g_o[row*DMODEL + tid*4];
    float4 x4 = *(const float4*)&x[row*DMODEL + tid*4];
    float y0 = o4.x + x4.x, y1 = o4.y + x4.y, y2 = o4.z + x4.z, y3 = o4.w + x4.w;

    float sum = y0 + y1 + y2 + y3;
    float sq  = y0*y0 + y1*y1 + y2*y2 + y3*y3;
    #pragma unroll
    for (int o = 16; o; o >>= 1) {
        sum += __shfl_xor_sync(0xffffffffu, sum, o);
        sq  += __shfl_xor_sync(0xffffffffu, sq,  o);
    }
    if (lane == 0) { rs[warp] = sum; rs[4 + warp] = sq; }
    __syncthreads();
    float ts = rs[0] + rs[1] + rs[2] + rs[3];
    float tq = rs[4] + rs[5] + rs[6] + rs[7];
    float mu  = ts * (1.0f/DMODEL);
    float var = tq * (1.0f/DMODEL) - mu*mu;
    float r = rsqrtf(var + 1e-5f);

    float4 g4 = *(const float4*)&gamma[tid*4];
    float4 b4 = *(const float4*)&beta[tid*4];
    float4 o_;
    o_.x = (y0 - mu)*r*g4.x + b4.x;
    o_.y = (y1 - mu)*r*g4.y + b4.y;
    o_.z = (y2 - mu)*r*g4.z + b4.z;
    o_.w = (y3 - mu)*r*g4.w + b4.w;
    *(float4*)&out[row*DMODEL + tid*4] = o_;
}

// ---------------------------------------------------------------------------
extern "C" void kernel_launch(void* const* d_in, const int* in_sizes, int n_in,
                              void* d_out, int out_size)
{
    const float* x     = (const float*)d_in[0];
    const float* pair  = (const float*)d_in[1];
    const float* Wq    = (const float*)d_in[2];
    const float* bq    = (const float*)d_in[3];
    const float* Wk    = (const float*)d_in[4];
    const float* bk    = (const float*)d_in[5];
    const float* Wv    = (const float*)d_in[6];
    const float* bv    = (const float*)d_in[7];
    const float* Wo    = (const float*)d_in[8];
    const float* bo    = (const float*)d_in[9];
    const float* gamma = (const float*)d_in[10];
    const float* beta  = (const float*)d_in[11];
    float* out = (float*)d_out;

    // Resolve device symbol addresses (host-side, capture-safe; no allocation)
    float *pQ, *pCtx, *pO;
    cudaGetSymbolAddress((void**)&pQ,   g_Q);
    cudaGetSymbolAddress((void**)&pCtx, g_ctx);
    cudaGetSymbolAddress((void**)&pO,   g_o);

    const int ATTN_SMEM = (256*PSTR + DMODEL + 8 + NHEAD*LSEQ + DMODEL + 64) * 4;
    cudaFuncSetAttribute(attn_kernel, cudaFuncAttributeMaxDynamicSharedMemorySize, ATTN_SMEM);

    dim3 ggrid(DMODEL/64, NROWS/32);
    gemm_bias_kernel<<<ggrid, 256>>>(x, Wq, bq, pQ);          // Q = x@Wq + bq
    qk_kernel<<<NROWS, 256>>>(Wk, bk);                        // qk, qb
    attn_kernel<<<NROWS, 256, ATTN_SMEM>>>(pair, Wv, bv);     // ctx
    gemm_bias_kernel<<<ggrid, 256>>>(pCtx, Wo, bo, pO);       // o = ctx@Wo + bo
    ln_kernel<<<NROWS, 128>>>(x, gamma, beta, out);           // LN(o + x)
}

// round 3
// speedup vs baseline: 1.2697x; 1.2697x over previous
#include <cuda_runtime.h>
#include <math.h>

#define BATCH 2
#define LSEQ 256
#define CB 64
#define DMODEL 512
#define NHEAD 8
#define HD 64
#define NROWS (BATCH*LSEQ)   // 512
#define PSTR 68              // padded pair row stride (floats)

// Static scratch
__device__ float g_qk[NROWS*DMODEL];
__device__ float g_wp[NROWS*DMODEL];
__device__ float g_o[NROWS*DMODEL];
__device__ float g_Wqk[DMODEL*DMODEL];
__device__ float g_bqk[DMODEL];
__device__ float g_Wvo[DMODEL*DMODEL];
__device__ float g_bvo[DMODEL];

// ---------------------------------------------------------------------------
// Prep: build combined weights (tiny GEMMs, ~34 MFLOP total).
//  bid <  64 : Wqk[e][h*64+c] = 0.125*sum_d Wq[e][h64+d]*Wk[c][h64+d]
//              (+ bqk on e-tile 0)
//  bid < 128 : Wvo[h*64+c][n] = sum_d Wv[c][h64+d]*Wo[h64+d][n]
//  bid < 136 : bvo[n] = sum_m bv[m]*Wo[m][n] + bo[n]
// ---------------------------------------------------------------------------
__global__ __launch_bounds__(256) void prep_kernel(
    const float* __restrict__ Wq, const float* __restrict__ bq,
    const float* __restrict__ Wk,
    const float* __restrict__ Wv, const float* __restrict__ bv,
    const float* __restrict__ Wo, const float* __restrict__ bo)
{
    __shared__ float Asm[64*68];
    __shared__ float Bsm[64*68];
    const int bid = blockIdx.x;
    const int tid = threadIdx.x;
    const int tx = tid & 15;   // 4-col group
    const int ty = tid >> 4;   // 4-row group (16 groups = 64 rows)

    if (bid < 64) {
        const int h = bid >> 3, et = bid & 7, e0 = et * 64;
        // Asm[e][d] = Wq[e0+e][h*64+d]   (64x64 = 1024 float4, 4/thread)
        #pragma unroll
        for (int p = 0; p < 4; p++) {
            int f = tid + p*256; int e = f >> 4, d4 = f & 15;
            float4 v = *(const float4*)&Wq[(e0+e)*DMODEL + h*64 + d4*4];
            *(float4*)&Asm[e*68 + d4*4] = v;
        }
        // Bsm[d][c] = Wk[c][h*64+d]  (transposed store)
        #pragma unroll
        for (int p = 0; p < 4; p++) {
            int f = tid + p*256; int c = f >> 4, d4 = f & 15;
            float4 v = *(const float4*)&Wk[c*DMODEL + h*64 + d4*4];
            Bsm[(d4*4+0)*68 + c] = v.x; Bsm[(d4*4+1)*68 + c] = v.y;
            Bsm[(d4*4+2)*68 + c] = v.z; Bsm[(d4*4+3)*68 + c] = v.w;
        }
        __syncthreads();
        float acc[4][4] = {};
        #pragma unroll 8
        for (int d = 0; d < 64; d++) {
            float4 b = *(const float4*)&Bsm[d*68 + tx*4];
            #pragma unroll
            for (int rr = 0; rr < 4; rr++) {
                float a = Asm[(ty*4+rr)*68 + d];
                acc[rr][0] += a*b.x; acc[rr][1] += a*b.y;
                acc[rr][2] += a*b.z; acc[rr][3] += a*b.w;
            }
        }
        #pragma unroll
        for (int rr = 0; rr < 4; rr++) {
            float4 o;
            o.x = acc[rr][0]*0.125f; o.y = acc[rr][1]*0.125f;
            o.z = acc[rr][2]*0.125f; o.w = acc[rr][3]*0.125f;
            *(float4*)&g_Wqk[(e0 + ty*4+rr)*DMODEL + h*64 + tx*4] = o;
        }
        if (et == 0 && tid < 64) {
            float acc2 = 0.f;
            #pragma unroll 8
            for (int d = 0; d < 64; d++) acc2 += bq[h*64+d] * Bsm[d*68 + tid];
            g_bqk[h*64 + tid] = acc2 * 0.125f;
        }
    } else if (bid < 128) {
        const int b2 = bid - 64, h = b2 >> 3, nt = b2 & 7, n0 = nt * 64;
        // Asm[c][d] = Wv[c][h*64+d]   (64x64, 4/thread)
        #pragma unroll
        for (int p = 0; p < 4; p++) {
            int f = tid + p*256; int c = f >> 4, d4 = f & 15;
            float4 v = *(const float4*)&Wv[c*DMODEL + h*64 + d4*4];
            *(float4*)&Asm[c*68 + d4*4] = v;
        }
        // Bsm[d][n] = Wo[h*64+d][n0+n]
        #pragma unroll
        for (int p = 0; p < 4; p++) {
            int f = tid + p*256; int d = f >> 4, n4 = f & 15;
            float4 v = *(const float4*)&Wo[(h*64+d)*DMODEL + n0 + n4*4];
            *(float4*)&Bsm[d*68 + n4*4] = v;
        }
        __syncthreads();
        float acc[4][4] = {};
        #pragma unroll 8
        for (int d = 0; d < 64; d++) {
            float4 b = *(const float4*)&Bsm[d*68 + tx*4];
            #pragma unroll
            for (int rr = 0; rr < 4; rr++) {
                float a = Asm[(ty*4+rr)*68 + d];
                acc[rr][0] += a*b.x; acc[rr][1] += a*b.y;
                acc[rr][2] += a*b.z; acc[rr][3] += a*b.w;
            }
        }
        #pragma unroll
        for (int rr = 0; rr < 4; rr++) {
            float4 o;
            o.x = acc[rr][0]; o.y = acc[rr][1]; o.z = acc[rr][2]; o.w = acc[rr][3];
            *(float4*)&g_Wvo[(h*64 + ty*4+rr)*DMODEL + n0 + tx*4] = o;
        }
    } else {
        const int nb = bid - 128, n0 = nb * 64;
        const int n = tid & 63, mg = tid >> 6;   // 4 m-groups of 128
        float acc = 0.f;
        for (int m = mg*128; m < mg*128 + 128; m++)
            acc += bv[m] * Wo[m*DMODEL + n0 + n];
        Asm[mg*64 + n] = acc;
        __syncthreads();
        if (tid < 64) {
            float s = Asm[tid] + Asm[64+tid] + Asm[128+tid] + Asm[192+tid] + bo[n0+tid];
            g_bvo[n0 + tid] = s;
        }
    }
}

// ---------------------------------------------------------------------------
// GEMM: C[512,512] = A[512,512] @ W[512,512] + bias
// BM=32, BN=64, BK=16; 128 threads; 4x4 outputs/thread; grid (8,16)=128 blocks
// ---------------------------------------------------------------------------
__global__ __launch_bounds__(128) void gemm512_kernel(
    const float* __restrict__ A, const float* __restrict__ W,
    const float* __restrict__ bias, float* __restrict__ C)
{
    __shared__ float As[32*20];
    __shared__ float Bs[16*64];
    const int bx = blockIdx.x;   // n tile (64)
    const int by = blockIdx.y;   // m tile (32)
    const int tid = threadIdx.x;
    const int tx = tid & 15;     // 4 cols
    const int ty = tid >> 4;     // 4 rows (8 groups)
    const int r0 = by*32 + ty*4;
    const int c0 = bx*64 + tx*4;

    float acc[4][4] = {};

    for (int kb = 0; kb < DMODEL; kb += 16) {
        // A tile 32x16: 128 float4, 1/thread
        {
            int r = tid >> 2, k4 = tid & 3;
            float4 v = *(const float4*)&A[(by*32 + r)*DMODEL + kb + k4*4];
            *(float4*)&As[r*20 + k4*4] = v;
        }
        // B tile 16x64: 256 float4, 2/thread
        #pragma unroll
        for (int p = 0; p < 2; p++) {
            int f = tid + p*128; int k = f >> 4, n4 = f & 15;
            float4 v = *(const float4*)&W[(kb + k)*DMODEL + bx*64 + n4*4];
            *(float4*)&Bs[k*64 + n4*4] = v;
        }
        __syncthreads();
        #pragma unroll
        for (int k = 0; k < 16; k++) {
            float4 b = *(const float4*)&Bs[k*64 + tx*4];
            float a0 = As[(ty*4+0)*20 + k];
            float a1 = As[(ty*4+1)*20 + k];
            float a2 = As[(ty*4+2)*20 + k];
            float a3 = As[(ty*4+3)*20 + k];
            acc[0][0] += a0*b.x; acc[0][1] += a0*b.y; acc[0][2] += a0*b.z; acc[0][3] += a0*b.w;
            acc[1][0] += a1*b.x; acc[1][1] += a1*b.y; acc[1][2] += a1*b.z; acc[1][3] += a1*b.w;
            acc[2][0] += a2*b.x; acc[2][1] += a2*b.y; acc[2][2] += a2*b.z; acc[2][3] += a2*b.w;
            acc[3][0] += a3*b.x; acc[3][1] += a3*b.y; acc[3][2] += a3*b.z; acc[3][3] += a3*b.w;
        }
        __syncthreads();
    }
    float4 bb = *(const float4*)&bias[c0];
    #pragma unroll
    for (int rr = 0; rr < 4; rr++) {
        float4 o;
        o.x = acc[rr][0] + bb.x; o.y = acc[rr][1] + bb.y;
        o.z = acc[rr][2] + bb.z; o.w = acc[rr][3] + bb.w;
        *(float4*)&C[(r0+rr)*DMODEL + c0] = o;
    }
}

// ---------------------------------------------------------------------------
// Attention per row: scores -> softmax -> normalized wp = w^T @ pair_row
// ---------------------------------------------------------------------------
__global__ __launch_bounds__(256) void attn_kernel(const float* __restrict__ pair)
{
    extern __shared__ float sm[];
    float* pairS = sm;                       // 256*68 = 17408
    float* qk_sm = sm + 256*PSTR;            // 512
    float* w_sm  = qk_sm + DMODEL;           // 256*8 = 2048 ([j][h])
    float* red   = w_sm + 2048;              // 8192 (wp partials; softmax red)

    const int row  = blockIdx.x;
    const int tid  = threadIdx.x;
    const int lane = tid & 31;
    const int warp = tid >> 5;

    // Load pair row tile (256 x 64) into padded SMEM
    const float4* pg = (const float4*)(pair + (size_t)row * (LSEQ*CB));
    #pragma unroll
    for (int it = 0; it < 16; it++) {
        int f = tid + it*256;
        int j = f >> 4, c4 = f & 15;
        float4 v = pg[f];
        *(float4*)&pairS[j*PSTR + c4*4] = v;
    }
    *(float2*)&qk_sm[tid*2] = *(const float2*)&g_qk[row*DMODEL + tid*2];
    __syncthreads();

    // Scores for this thread's j across all heads
    float s[NHEAD] = {};
    {
        const float4* prow = (const float4*)&pairS[tid*PSTR];
        #pragma unroll
        for (int c4 = 0; c4 < 16; c4++) {
            float4 p = prow[c4];
            #pragma unroll
            for (int h = 0; h < NHEAD; h++) {
                float4 q = *(const float4*)&qk_sm[h*64 + c4*4];
                s[h] += p.x*q.x + p.y*q.y + p.z*q.z + p.w*q.w;
            }
        }
    }

    // Softmax over j (per head)
    #pragma unroll
    for (int h = 0; h < NHEAD; h++) {
        float v = s[h];
        #pragma unroll
        for (int o = 16; o; o >>= 1) v = fmaxf(v, __shfl_xor_sync(0xffffffffu, v, o));
        if (lane == 0) red[warp*NHEAD + h] = v;
    }
    __syncthreads();
    float m[NHEAD];
    #pragma unroll
    for (int h = 0; h < NHEAD; h++) {
        float v = red[h];
        #pragma unroll
        for (int w2 = 1; w2 < 8; w2++) v = fmaxf(v, red[w2*NHEAD + h]);
        m[h] = v;
    }
    __syncthreads();

    float e[NHEAD], Zi[NHEAD];
    #pragma unroll
    for (int h = 0; h < NHEAD; h++) {
        e[h] = __expf(s[h] - m[h]);
        float v = e[h];
        #pragma unroll
        for (int o = 16; o; o >>= 1) v += __shfl_xor_sync(0xffffffffu, v, o);
        if (lane == 0) red[warp*NHEAD + h] = v;
    }
    __syncthreads();
    #pragma unroll
    for (int h = 0; h < NHEAD; h++) {
        float v = 0.f;
        #pragma unroll
        for (int w2 = 0; w2 < 8; w2++) v += red[w2*NHEAD + h];
        Zi[h] = 1.0f / v;
    }
    __syncthreads();   // before red reuse

    // Store normalized weights transposed: w_sm[j][h]
    {
        float4 wlo = make_float4(e[0]*Zi[0], e[1]*Zi[1], e[2]*Zi[2], e[3]*Zi[3]);
        float4 whi = make_float4(e[4]*Zi[4], e[5]*Zi[5], e[6]*Zi[6], e[7]*Zi[7]);
        *(float4*)&w_sm[tid*8 + 0] = wlo;
        *(float4*)&w_sm[tid*8 + 4] = whi;
    }
    __syncthreads();

    // wp partials: thread = (c4, jgroup); all 8 heads in registers
    {
        const int c4 = tid & 15, jg = tid >> 4;
        float4 acc[NHEAD];
        #pragma unroll
        for (int h = 0; h < NHEAD; h++) acc[h] = make_float4(0.f,0.f,0.f,0.f);
        #pragma unroll 4
        for (int jj = 0; jj < 16; jj++) {
            int j = jg*16 + jj;
            float4 p  = *(const float4*)&pairS[j*PSTR + c4*4];
            float4 wA = *(const float4*)&w_sm[j*8];
            float4 wB = *(const float4*)&w_sm[j*8 + 4];
            acc[0].x += wA.x*p.x; acc[0].y += wA.x*p.y; acc[0].z += wA.x*p.z; acc[0].w += wA.x*p.w;
            acc[1].x += wA.y*p.x; acc[1].y += wA.y*p.y; acc[1].z += wA.y*p.z; acc[1].w += wA.y*p.w;
            acc[2].x += wA.z*p.x; acc[2].y += wA.z*p.y; acc[2].z += wA.z*p.z; acc[2].w += wA.z*p.w;
            acc[3].x += wA.w*p.x; acc[3].y += wA.w*p.y; acc[3].z += wA.w*p.z; acc[3].w += wA.w*p.w;
            acc[4].x += wB.x*p.x; acc[4].y += wB.x*p.y; acc[4].z += wB.x*p.z; acc[4].w += wB.x*p.w;
            acc[5].x += wB.y*p.x; acc[5].y += wB.y*p.y; acc[5].z += wB.y*p.z; acc[5].w += wB.y*p.w;
            acc[6].x += wB.z*p.x; acc[6].y += wB.z*p.y; acc[6].z += wB.z*p.z; acc[6].w += wB.z*p.w;
            acc[7].x += wB.w*p.x; acc[7].y += wB.w*p.y; acc[7].z += wB.w*p.z; acc[7].w += wB.w*p.w;
        }
        #pragma unroll
        for (int h = 0; h < NHEAD; h++)
            *(float4*)&red[((jg*NHEAD + h)*16 + c4)*4] = acc[h];
    }
    __syncthreads();

    // Final reduce over 16 jgroups -> g_wp
    if (tid < 128) {
        const int h = tid >> 4, c4 = tid & 15;
        float4 sum = make_float4(0.f,0.f,0.f,0.f);
        #pragma unroll
        for (int jg = 0; jg < 16; jg++) {
            float4 v = *(const float4*)&red[((jg*NHEAD + h)*16 + c4)*4];
            sum.x += v.x; sum.y += v.y; sum.z += v.z; sum.w += v.w;
        }
        *(float4*)&g_wp[row*DMODEL + h*64 + c4*4] = sum;
    }
}

// ---------------------------------------------------------------------------
// LayerNorm(o + x) * gamma + beta -> out. 512 blocks x 128 threads.
// ---------------------------------------------------------------------------
__global__ __launch_bounds__(128) void ln_kernel(
    const float* __restrict__ x, const float* __restrict__ gamma,
    const float* __restrict__ beta, float* __restrict__ out)
{
    __shared__ float rs[8];
    const int row = blockIdx.x;
    const int tid = threadIdx.x;
    const int lane = tid & 31, warp = tid >> 5;

    float4 o4 = *(const float4*)&g_o[row*DMODEL + tid*4];
    float4 x4 = *(const float4*)&x[row*DMODEL + tid*4];
    float y0 = o4.x + x4.x, y1 = o4.y + x4.y, y2 = o4.z + x4.z, y3 = o4.w + x4.w;

    float sum = y0 + y1 + y2 + y3;
    float sq  = y0*y0 + y1*y1 + y2*y2 + y3*y3;
    #pragma unroll
    for (int o = 16; o; o >>= 1) {
        sum += __shfl_xor_sync(0xffffffffu, sum, o);
        sq  += __shfl_xor_sync(0xffffffffu, sq,  o);
    }
    if (lane == 0) { rs[warp] = sum; rs[4 + warp] = sq; }
    __syncthreads();
    float ts = rs[0] + rs[1] + rs[2] + rs[3];
    float tq = rs[4] + rs[5] + rs[6] + rs[7];
    float mu  = ts * (1.0f/DMODEL);
    float var = tq * (1.0f/DMODEL) - mu*mu;
    float r = rsqrtf(var + 1e-5f);

    float4 g4 = *(const float4*)&gamma[tid*4];
    float4 b4 = *(const float4*)&beta[tid*4];
    float4 o_;
    o_.x = (y0 - mu)*r*g4.x + b4.x;
    o_.y = (y1 - mu)*r*g4.y + b4.y;
    o_.z = (y2 - mu)*r*g4.z + b4.z;
    o_.w = (y3 - mu)*r*g4.w + b4.w;
    *(float4*)&out[row*DMODEL + tid*4] = o_;
}

// ---------------------------------------------------------------------------
extern "C" void kernel_launch(void* const* d_in, const int* in_sizes, int n_in,
                              void* d_out, int out_size)
{
    const float* x     = (const float*)d_in[0];
    const float* pair  = (const float*)d_in[1];
    const float* Wq    = (const float*)d_in[2];
    const float* bq    = (const float*)d_in[3];
    const float* Wk    = (const float*)d_in[4];
    // bk (d_in[5]) contributes a per-(row,h) constant to scores -> softmax-invariant, unused
    const float* Wv    = (const float*)d_in[6];
    const float* bv    = (const float*)d_in[7];
    const float* Wo    = (const float*)d_in[8];
    const float* bo    = (const float*)d_in[9];
    const float* gamma = (const float*)d_in[10];
    const float* beta  = (const float*)d_in[11];
    float* out = (float*)d_out;

    float *pQK, *pWP, *pO, *pWqk, *pBqk, *pWvo, *pBvo;
    cudaGetSymbolAddress((void**)&pQK,  g_qk);
    cudaGetSymbolAddress((void**)&pWP,  g_wp);
    cudaGetSymbolAddress((void**)&pO,   g_o);
    cudaGetSymbolAddress((void**)&pWqk, g_Wqk);
    cudaGetSymbolAddress((void**)&pBqk, g_bqk);
    cudaGetSymbolAddress((void**)&pWvo, g_Wvo);
    cudaGetSymbolAddress((void**)&pBvo, g_bvo);

    const int ATTN_SMEM = (256*PSTR + DMODEL + 2048 + 8192) * 4;  // 112640 B
    cudaFuncSetAttribute(attn_kernel, cudaFuncAttributeMaxDynamicSharedMemorySize, ATTN_SMEM);

    dim3 ggrid(DMODEL/64, NROWS/32);   // (8,16)

    prep_kernel<<<136, 256>>>(Wq, bq, Wk, Wv, bv, Wo, bo);
    gemm512_kernel<<<ggrid, 128>>>(x, pWqk, pBqk, pQK);     // qk = x@Wqk + bqk
    attn_kernel<<<NROWS, 256, ATTN_SMEM>>>(pair);           // wp
    gemm512_kernel<<<ggrid, 128>>>(pWP, pWvo, pBvo, pO);    // o = wp@Wvo + bvo
    ln_kernel<<<NROWS, 128>>>(x, gamma, beta, out);         // LN(o + x)
}

// round 4
// speedup vs baseline: 1.8077x; 1.4237x over previous
#include <cuda_runtime.h>
#include <math.h>

#define BATCH 2
#define LSEQ 256
#define CB 64
#define DMODEL 512
#define NHEAD 8
#define HD 64
#define NROWS (BATCH*LSEQ)   // 512
#define PSTR 68              // padded pair row stride (floats)
#define KSPLIT 4
#define KCHUNK (DMODEL/KSPLIT)   // 128

// Static scratch
__device__ float g_part[KSPLIT*NROWS*DMODEL];   // split-K partials (reused by both GEMMs)
__device__ float g_wp[NROWS*DMODEL];
__device__ float g_Wqk[DMODEL*DMODEL];
__device__ float g_bqk[DMODEL];
__device__ float g_Wvo[DMODEL*DMODEL];
__device__ float g_bvo[DMODEL];

// ---------------------------------------------------------------------------
// Prep: build combined weights (tiny GEMMs, ~34 MFLOP total).
// ---------------------------------------------------------------------------
__global__ __launch_bounds__(256) void prep_kernel(
    const float* __restrict__ Wq, const float* __restrict__ bq,
    const float* __restrict__ Wk,
    const float* __restrict__ Wv, const float* __restrict__ bv,
    const float* __restrict__ Wo, const float* __restrict__ bo)
{
    __shared__ float Asm[64*68];
    __shared__ float Bsm[64*68];
    const int bid = blockIdx.x;
    const int tid = threadIdx.x;
    const int tx = tid & 15;
    const int ty = tid >> 4;

    if (bid < 64) {
        const int h = bid >> 3, et = bid & 7, e0 = et * 64;
        #pragma unroll
        for (int p = 0; p < 4; p++) {
            int f = tid + p*256; int e = f >> 4, d4 = f & 15;
            float4 v = *(const float4*)&Wq[(e0+e)*DMODEL + h*64 + d4*4];
            *(float4*)&Asm[e*68 + d4*4] = v;
        }
        #pragma unroll
        for (int p = 0; p < 4; p++) {
            int f = tid + p*256; int c = f >> 4, d4 = f & 15;
            float4 v = *(const float4*)&Wk[c*DMODEL + h*64 + d4*4];
            Bsm[(d4*4+0)*68 + c] = v.x; Bsm[(d4*4+1)*68 + c] = v.y;
            Bsm[(d4*4+2)*68 + c] = v.z; Bsm[(d4*4+3)*68 + c] = v.w;
        }
        __syncthreads();
        float acc[4][4] = {};
        #pragma unroll 8
        for (int d = 0; d < 64; d++) {
            float4 b = *(const float4*)&Bsm[d*68 + tx*4];
            #pragma unroll
            for (int rr = 0; rr < 4; rr++) {
                float a = Asm[(ty*4+rr)*68 + d];
                acc[rr][0] += a*b.x; acc[rr][1] += a*b.y;
                acc[rr][2] += a*b.z; acc[rr][3] += a*b.w;
            }
        }
        #pragma unroll
        for (int rr = 0; rr < 4; rr++) {
            float4 o;
            o.x = acc[rr][0]*0.125f; o.y = acc[rr][1]*0.125f;
            o.z = acc[rr][2]*0.125f; o.w = acc[rr][3]*0.125f;
            *(float4*)&g_Wqk[(e0 + ty*4+rr)*DMODEL + h*64 + tx*4] = o;
        }
        if (et == 0 && tid < 64) {
            float acc2 = 0.f;
            #pragma unroll 8
            for (int d = 0; d < 64; d++) acc2 += bq[h*64+d] * Bsm[d*68 + tid];
            g_bqk[h*64 + tid] = acc2 * 0.125f;
        }
    } else if (bid < 128) {
        const int b2 = bid - 64, h = b2 >> 3, nt = b2 & 7, n0 = nt * 64;
        #pragma unroll
        for (int p = 0; p < 4; p++) {
            int f = tid + p*256; int c = f >> 4, d4 = f & 15;
            float4 v = *(const float4*)&Wv[c*DMODEL + h*64 + d4*4];
            *(float4*)&Asm[c*68 + d4*4] = v;
        }
        #pragma unroll
        for (int p = 0; p < 4; p++) {
            int f = tid + p*256; int d = f >> 4, n4 = f & 15;
            float4 v = *(const float4*)&Wo[(h*64+d)*DMODEL + n0 + n4*4];
            *(float4*)&Bsm[d*68 + n4*4] = v;
        }
        __syncthreads();
        float acc[4][4] = {};
        #pragma unroll 8
        for (int d = 0; d < 64; d++) {
            float4 b = *(const float4*)&Bsm[d*68 + tx*4];
            #pragma unroll
            for (int rr = 0; rr < 4; rr++) {
                float a = Asm[(ty*4+rr)*68 + d];
                acc[rr][0] += a*b.x; acc[rr][1] += a*b.y;
                acc[rr][2] += a*b.z; acc[rr][3] += a*b.w;
            }
        }
        #pragma unroll
        for (int rr = 0; rr < 4; rr++) {
            float4 o;
            o.x = acc[rr][0]; o.y = acc[rr][1]; o.z = acc[rr][2]; o.w = acc[rr][3];
            *(float4*)&g_Wvo[(h*64 + ty*4+rr)*DMODEL + n0 + tx*4] = o;
        }
    } else {
        const int nb = bid - 128, n0 = nb * 64;
        const int n = tid & 63, mg = tid >> 6;
        float acc = 0.f;
        for (int m = mg*128; m < mg*128 + 128; m++)
            acc += bv[m] * Wo[m*DMODEL + n0 + n];
        Asm[mg*64 + n] = acc;
        __syncthreads();
        if (tid < 64) {
            float s = Asm[tid] + Asm[64+tid] + Asm[128+tid] + Asm[192+tid] + bo[n0+tid];
            g_bvo[n0 + tid] = s;
        }
    }
}

// ---------------------------------------------------------------------------
// Split-K GEMM: P[kz][512,512] partial = A[:, kz*128:(kz+1)*128] @ W[chunk]
// BM=32, BN=64, BK=16; 128 threads; 4x4/thread; grid (8,16,KSPLIT)=512 blocks
// ---------------------------------------------------------------------------
__global__ __launch_bounds__(128) void gemm_splitk_kernel(
    const float* __restrict__ A, const float* __restrict__ W)
{
    __shared__ float As[32*20];
    __shared__ float Bs[16*64];
    const int bx = blockIdx.x;
    const int by = blockIdx.y;
    const int kz = blockIdx.z;
    const int tid = threadIdx.x;
    const int tx = tid & 15;
    const int ty = tid >> 4;
    const int r0 = by*32 + ty*4;
    const int c0 = bx*64 + tx*4;

    float acc[4][4] = {};

    const int k0 = kz * KCHUNK;
    for (int kb = k0; kb < k0 + KCHUNK; kb += 16) {
        {
            int r = tid >> 2, k4 = tid & 3;
            float4 v = *(const float4*)&A[(by*32 + r)*DMODEL + kb + k4*4];
            *(float4*)&As[r*20 + k4*4] = v;
        }
        #pragma unroll
        for (int p = 0; p < 2; p++) {
            int f = tid + p*128; int k = f >> 4, n4 = f & 15;
            float4 v = *(const float4*)&W[(kb + k)*DMODEL + bx*64 + n4*4];
            *(float4*)&Bs[k*64 + n4*4] = v;
        }
        __syncthreads();
        #pragma unroll
        for (int k = 0; k < 16; k++) {
            float4 b = *(const float4*)&Bs[k*64 + tx*4];
            float a0 = As[(ty*4+0)*20 + k];
            float a1 = As[(ty*4+1)*20 + k];
            float a2 = As[(ty*4+2)*20 + k];
            float a3 = As[(ty*4+3)*20 + k];
            acc[0][0] += a0*b.x; acc[0][1] += a0*b.y; acc[0][2] += a0*b.z; acc[0][3] += a0*b.w;
            acc[1][0] += a1*b.x; acc[1][1] += a1*b.y; acc[1][2] += a1*b.z; acc[1][3] += a1*b.w;
            acc[2][0] += a2*b.x; acc[2][1] += a2*b.y; acc[2][2] += a2*b.z; acc[2][3] += a2*b.w;
            acc[3][0] += a3*b.x; acc[3][1] += a3*b.y; acc[3][2] += a3*b.z; acc[3][3] += a3*b.w;
        }
        __syncthreads();
    }
    float* P = &g_part[(size_t)kz * NROWS * DMODEL];
    #pragma unroll
    for (int rr = 0; rr < 4; rr++)
        *(float4*)&P[(r0+rr)*DMODEL + c0] = make_float4(acc[rr][0], acc[rr][1], acc[rr][2], acc[rr][3]);
}

// ---------------------------------------------------------------------------
// Attention per row: reduce qk partials (+bqk) -> scores -> softmax -> wp
// ---------------------------------------------------------------------------
__global__ __launch_bounds__(256) void attn_kernel(const float* __restrict__ pair)
{
    extern __shared__ float sm[];
    float* pairS = sm;                       // 256*68
    float* qk_sm = sm + 256*PSTR;            // 512
    float* w_sm  = qk_sm + DMODEL;           // 2048
    float* red   = w_sm + 2048;              // 8192

    const int row  = blockIdx.x;
    const int tid  = threadIdx.x;
    const int lane = tid & 31;
    const int warp = tid >> 5;

    // Load pair row tile (256 x 64) into padded SMEM
    const float4* pg = (const float4*)(pair + (size_t)row * (LSEQ*CB));
    #pragma unroll
    for (int it = 0; it < 16; it++) {
        int f = tid + it*256;
        int j = f >> 4, c4 = f & 15;
        float4 v = pg[f];
        *(float4*)&pairS[j*PSTR + c4*4] = v;
    }
    // Reduce split-K partials for this row's qk vector
    {
        float2 acc = *(const float2*)&g_bqk[tid*2];
        #pragma unroll
        for (int kz = 0; kz < KSPLIT; kz++) {
            float2 v = *(const float2*)&g_part[((size_t)kz*NROWS + row)*DMODEL + tid*2];
            acc.x += v.x; acc.y += v.y;
        }
        *(float2*)&qk_sm[tid*2] = acc;
    }
    __syncthreads();

    // Scores for this thread's j across all heads
    float s[NHEAD] = {};
    {
        const float4* prow = (const float4*)&pairS[tid*PSTR];
        #pragma unroll
        for (int c4 = 0; c4 < 16; c4++) {
            float4 p = prow[c4];
            #pragma unroll
            for (int h = 0; h < NHEAD; h++) {
                float4 q = *(const float4*)&qk_sm[h*64 + c4*4];
                s[h] += p.x*q.x + p.y*q.y + p.z*q.z + p.w*q.w;
            }
        }
    }

    // Softmax over j (per head)
    #pragma unroll
    for (int h = 0; h < NHEAD; h++) {
        float v = s[h];
        #pragma unroll
        for (int o = 16; o; o >>= 1) v = fmaxf(v, __shfl_xor_sync(0xffffffffu, v, o));
        if (lane == 0) red[warp*NHEAD + h] = v;
    }
    __syncthreads();
    float m[NHEAD];
    #pragma unroll
    for (int h = 0; h < NHEAD; h++) {
        float v = red[h];
        #pragma unroll
        for (int w2 = 1; w2 < 8; w2++) v = fmaxf(v, red[w2*NHEAD + h]);
        m[h] = v;
    }
    __syncthreads();

    float e[NHEAD], Zi[NHEAD];
    #pragma unroll
    for (int h = 0; h < NHEAD; h++) {
        e[h] = __expf(s[h] - m[h]);
        float v = e[h];
        #pragma unroll
        for (int o = 16; o; o >>= 1) v += __shfl_xor_sync(0xffffffffu, v, o);
        if (lane == 0) red[warp*NHEAD + h] = v;
    }
    __syncthreads();
    #pragma unroll
    for (int h = 0; h < NHEAD; h++) {
        float v = 0.f;
        #pragma unroll
        for (int w2 = 0; w2 < 8; w2++) v += red[w2*NHEAD + h];
        Zi[h] = 1.0f / v;
    }
    __syncthreads();

    // Store normalized weights transposed: w_sm[j][h]
    {
        float4 wlo = make_float4(e[0]*Zi[0], e[1]*Zi[1], e[2]*Zi[2], e[3]*Zi[3]);
        float4 whi = make_float4(e[4]*Zi[4], e[5]*Zi[5], e[6]*Zi[6], e[7]*Zi[7]);
        *(float4*)&w_sm[tid*8 + 0] = wlo;
        *(float4*)&w_sm[tid*8 + 4] = whi;
    }
    __syncthreads();

    // wp partials: thread = (c4, jgroup); all 8 heads in registers
    {
        const int c4 = tid & 15, jg = tid >> 4;
        float4 acc[NHEAD];
        #pragma unroll
        for (int h = 0; h < NHEAD; h++) acc[h] = make_float4(0.f,0.f,0.f,0.f);
        #pragma unroll 4
        for (int jj = 0; jj < 16; jj++) {
            int j = jg*16 + jj;
            float4 p  = *(const float4*)&pairS[j*PSTR + c4*4];
            float4 wA = *(const float4*)&w_sm[j*8];
            float4 wB = *(const float4*)&w_sm[j*8 + 4];
            acc[0].x += wA.x*p.x; acc[0].y += wA.x*p.y; acc[0].z += wA.x*p.z; acc[0].w += wA.x*p.w;
            acc[1].x += wA.y*p.x; acc[1].y += wA.y*p.y; acc[1].z += wA.y*p.z; acc[1].w += wA.y*p.w;
            acc[2].x += wA.z*p.x; acc[2].y += wA.z*p.y; acc[2].z += wA.z*p.z; acc[2].w += wA.z*p.w;
            acc[3].x += wA.w*p.x; acc[3].y += wA.w*p.y; acc[3].z += wA.w*p.z; acc[3].w += wA.w*p.w;
            acc[4].x += wB.x*p.x; acc[4].y += wB.x*p.y; acc[4].z += wB.x*p.z; acc[4].w += wB.x*p.w;
            acc[5].x += wB.y*p.x; acc[5].y += wB.y*p.y; acc[5].z += wB.y*p.z; acc[5].w += wB.y*p.w;
            acc[6].x += wB.z*p.x; acc[6].y += wB.z*p.y; acc[6].z += wB.z*p.z; acc[6].w += wB.z*p.w;
            acc[7].x += wB.w*p.x; acc[7].y += wB.w*p.y; acc[7].z += wB.w*p.z; acc[7].w += wB.w*p.w;
        }
        #pragma unroll
        for (int h = 0; h < NHEAD; h++)
            *(float4*)&red[((jg*NHEAD + h)*16 + c4)*4] = acc[h];
    }
    __syncthreads();

    // Final reduce over 16 jgroups -> g_wp
    if (tid < 128) {
        const int h = tid >> 4, c4 = tid & 15;
        float4 sum = make_float4(0.f,0.f,0.f,0.f);
        #pragma unroll
        for (int jg = 0; jg < 16; jg++) {
            float4 v = *(const float4*)&red[((jg*NHEAD + h)*16 + c4)*4];
            sum.x += v.x; sum.y += v.y; sum.z += v.z; sum.w += v.w;
        }
        *(float4*)&g_wp[row*DMODEL + h*64 + c4*4] = sum;
    }
}

// ---------------------------------------------------------------------------
// LayerNorm(sum_kz part + bvo + x) * gamma + beta -> out.
// 512 blocks x 128 threads.
// ---------------------------------------------------------------------------
__global__ __launch_bounds__(128) void ln_kernel(
    const float* __restrict__ x, const float* __restrict__ gamma,
    const float* __restrict__ beta, float* __restrict__ out)
{
    __shared__ float rs[8];
    const int row = blockIdx.x;
    const int tid = threadIdx.x;
    const int lane = tid & 31, warp = tid >> 5;

    float4 x4 = *(const float4*)&x[row*DMODEL + tid*4];
    float4 b4v = *(const float4*)&g_bvo[tid*4];
    float y0 = x4.x + b4v.x, y1 = x4.y + b4v.y, y2 = x4.z + b4v.z, y3 = x4.w + b4v.w;
    #pragma unroll
    for (int kz = 0; kz < KSPLIT; kz++) {
        float4 p4 = *(const float4*)&g_part[((size_t)kz*NROWS + row)*DMODEL + tid*4];
        y0 += p4.x; y1 += p4.y; y2 += p4.z; y3 += p4.w;
    }

    float sum = y0 + y1 + y2 + y3;
    float sq  = y0*y0 + y1*y1 + y2*y2 + y3*y3;
    #pragma unroll
    for (int o = 16; o; o >>= 1) {
        sum += __shfl_xor_sync(0xffffffffu, sum, o);
        sq  += __shfl_xor_sync(0xffffffffu, sq,  o);
    }
    if (lane == 0) { rs[warp] = sum; rs[4 + warp] = sq; }
    __syncthreads();
    float ts = rs[0] + rs[1] + rs[2] + rs[3];
    float tq = rs[4] + rs[5] + rs[6] + rs[7];
    float mu  = ts * (1.0f/DMODEL);
    float var = tq * (1.0f/DMODEL) - mu*mu;
    float r = rsqrtf(var + 1e-5f);

    float4 g4 = *(const float4*)&gamma[tid*4];
    float4 b4 = *(const float4*)&beta[tid*4];
    float4 o_;
    o_.x = (y0 - mu)*r*g4.x + b4.x;
    o_.y = (y1 - mu)*r*g4.y + b4.y;
    o_.z = (y2 - mu)*r*g4.z + b4.z;
    o_.w = (y3 - mu)*r*g4.w + b4.w;
    *(float4*)&out[row*DMODEL + tid*4] = o_;
}

// ---------------------------------------------------------------------------
extern "C" void kernel_launch(void* const* d_in, const int* in_sizes, int n_in,
                              void* d_out, int out_size)
{
    const float* x     = (const float*)d_in[0];
    const float* pair  = (const float*)d_in[1];
    const float* Wq    = (const float*)d_in[2];
    const float* bq    = (const float*)d_in[3];
    const float* Wk    = (const float*)d_in[4];
    // bk (d_in[5]) is softmax-invariant (per-(row,h) constant), dropped
    const float* Wv    = (const float*)d_in[6];
    const float* bv    = (const float*)d_in[7];
    const float* Wo    = (const float*)d_in[8];
    const float* bo    = (const float*)d_in[9];
    const float* gamma = (const float*)d_in[10];
    const float* beta  = (const float*)d_in[11];
    float* out = (float*)d_out;

    float *pWP, *pWqk, *pWvo;
    cudaGetSymbolAddress((void**)&pWP,  g_wp);
    cudaGetSymbolAddress((void**)&pWqk, g_Wqk);
    cudaGetSymbolAddress((void**)&pWvo, g_Wvo);

    const int ATTN_SMEM = (256*PSTR + DMODEL + 2048 + 8192) * 4;  // 112640 B
    cudaFuncSetAttribute(attn_kernel, cudaFuncAttributeMaxDynamicSharedMemorySize, ATTN_SMEM);

    dim3 ggrid(DMODEL/64, NROWS/32, KSPLIT);   // (8,16,4) = 512 blocks

    prep_kernel<<<136, 256>>>(Wq, bq, Wk, Wv, bv, Wo, bo);
    gemm_splitk_kernel<<<ggrid, 128>>>(x, pWqk);            // qk partials
    attn_kernel<<<NROWS, 256, ATTN_SMEM>>>(pair);           // reduce + softmax + wp
    gemm_splitk_kernel<<<ggrid, 128>>>(pWP, pWvo);          // o partials
    ln_kernel<<<NROWS, 128>>>(x, gamma, beta, out);         // reduce + LN(o + x)
}

// round 5
// speedup vs baseline: 1.8777x; 1.0387x over previous
#include <cuda_runtime.h>
#include <math.h>

#define BATCH 2
#define LSEQ 256
#define CB 64
#define DMODEL 512
#define NHEAD 8
#define HD 64
#define NROWS (BATCH*LSEQ)   // 512
#define PSTR 68              // padded pair row stride (floats)
#define KSPLIT 8
#define KCHUNK (DMODEL/KSPLIT)   // 64

// Static scratch
__device__ float g_part[KSPLIT*NROWS*DMODEL];   // split-K partials (reused by both GEMMs)
__device__ float g_wp[NROWS*DMODEL];
__device__ float g_Wqk[DMODEL*DMODEL];
__device__ float g_bqk[DMODEL];
__device__ float g_Wvo[DMODEL*DMODEL];
__device__ float g_bvo[DMODEL];

// ---------------------------------------------------------------------------
// Prep: build combined weights (tiny GEMMs, ~34 MFLOP total).
// ---------------------------------------------------------------------------
__global__ __launch_bounds__(256) void prep_kernel(
    const float* __restrict__ Wq, const float* __restrict__ bq,
    const float* __restrict__ Wk,
    const float* __restrict__ Wv, const float* __restrict__ bv,
    const float* __restrict__ Wo, const float* __restrict__ bo)
{
    __shared__ float Asm[64*68];
    __shared__ float Bsm[64*68];
    const int bid = blockIdx.x;
    const int tid = threadIdx.x;
    const int tx = tid & 15;
    const int ty = tid >> 4;

    if (bid < 64) {
        const int h = bid >> 3, et = bid & 7, e0 = et * 64;
        #pragma unroll
        for (int p = 0; p < 4; p++) {
            int f = tid + p*256; int e = f >> 4, d4 = f & 15;
            float4 v = *(const float4*)&Wq[(e0+e)*DMODEL + h*64 + d4*4];
            *(float4*)&Asm[e*68 + d4*4] = v;
        }
        #pragma unroll
        for (int p = 0; p < 4; p++) {
            int f = tid + p*256; int c = f >> 4, d4 = f & 15;
            float4 v = *(const float4*)&Wk[c*DMODEL + h*64 + d4*4];
            Bsm[(d4*4+0)*68 + c] = v.x; Bsm[(d4*4+1)*68 + c] = v.y;
            Bsm[(d4*4+2)*68 + c] = v.z; Bsm[(d4*4+3)*68 + c] = v.w;
        }
        __syncthreads();
        float acc[4][4] = {};
        #pragma unroll 8
        for (int d = 0; d < 64; d++) {
            float4 b = *(const float4*)&Bsm[d*68 + tx*4];
            #pragma unroll
            for (int rr = 0; rr < 4; rr++) {
                float a = Asm[(ty*4+rr)*68 + d];
                acc[rr][0] += a*b.x; acc[rr][1] += a*b.y;
                acc[rr][2] += a*b.z; acc[rr][3] += a*b.w;
            }
        }
        #pragma unroll
        for (int rr = 0; rr < 4; rr++) {
            float4 o;
            o.x = acc[rr][0]*0.125f; o.y = acc[rr][1]*0.125f;
            o.z = acc[rr][2]*0.125f; o.w = acc[rr][3]*0.125f;
            *(float4*)&g_Wqk[(e0 + ty*4+rr)*DMODEL + h*64 + tx*4] = o;
        }
        if (et == 0 && tid < 64) {
            float acc2 = 0.f;
            #pragma unroll 8
            for (int d = 0; d < 64; d++) acc2 += bq[h*64+d] * Bsm[d*68 + tid];
            g_bqk[h*64 + tid] = acc2 * 0.125f;
        }
    } else if (bid < 128) {
        const int b2 = bid - 64, h = b2 >> 3, nt = b2 & 7, n0 = nt * 64;
        #pragma unroll
        for (int p = 0; p < 4; p++) {
            int f = tid + p*256; int c = f >> 4, d4 = f & 15;
            float4 v = *(const float4*)&Wv[c*DMODEL + h*64 + d4*4];
            *(float4*)&Asm[c*68 + d4*4] = v;
        }
        #pragma unroll
        for (int p = 0; p < 4; p++) {
            int f = tid + p*256; int d = f >> 4, n4 = f & 15;
            float4 v = *(const float4*)&Wo[(h*64+d)*DMODEL + n0 + n4*4];
            *(float4*)&Bsm[d*68 + n4*4] = v;
        }
        __syncthreads();
        float acc[4][4] = {};
        #pragma unroll 8
        for (int d = 0; d < 64; d++) {
            float4 b = *(const float4*)&Bsm[d*68 + tx*4];
            #pragma unroll
            for (int rr = 0; rr < 4; rr++) {
                float a = Asm[(ty*4+rr)*68 + d];
                acc[rr][0] += a*b.x; acc[rr][1] += a*b.y;
                acc[rr][2] += a*b.z; acc[rr][3] += a*b.w;
            }
        }
        #pragma unroll
        for (int rr = 0; rr < 4; rr++) {
            float4 o;
            o.x = acc[rr][0]; o.y = acc[rr][1]; o.z = acc[rr][2]; o.w = acc[rr][3];
            *(float4*)&g_Wvo[(h*64 + ty*4+rr)*DMODEL + n0 + tx*4] = o;
        }
    } else {
        const int nb = bid - 128, n0 = nb * 64;
        const int n = tid & 63, mg = tid >> 6;
        float acc = 0.f;
        for (int m = mg*128; m < mg*128 + 128; m++)
            acc += bv[m] * Wo[m*DMODEL + n0 + n];
        Asm[mg*64 + n] = acc;
        __syncthreads();
        if (tid < 64) {
            float s = Asm[tid] + Asm[64+tid] + Asm[128+tid] + Asm[192+tid] + bo[n0+tid];
            g_bvo[n0 + tid] = s;
        }
    }
}

// ---------------------------------------------------------------------------
// Split-K GEMM: partial[kz] = A[:, kz*64:(kz+1)*64] @ W[chunk]
// BM=64, BN=64, BK=16; 256 threads; 4x4/thread; grid (8,8,8)=512 blocks.
// Double-buffered SMEM, global loads prefetched into registers.
// ---------------------------------------------------------------------------
__global__ __launch_bounds__(256) void gemm_splitk_kernel(
    const float* __restrict__ A, const float* __restrict__ W)
{
    __shared__ float As[2][64*20];
    __shared__ float Bs[2][16*64];
    const int bx = blockIdx.x;   // n tile (64)
    const int by = blockIdx.y;   // m tile (64)
    const int kz = blockIdx.z;
    const int tid = threadIdx.x;
    const int tx = tid & 15;     // 4 cols
    const int ty = tid >> 4;     // 4 rows (16 groups)
    const int r0 = by*64 + ty*4;
    const int c0 = bx*64 + tx*4;
    const int k0 = kz * KCHUNK;

    // load indices
    const int ar = tid >> 2, ak4 = tid & 3;      // A: 64 rows x 4 float4
    const int bk_ = tid >> 4, bn4 = tid & 15;    // B: 16 rows x 16 float4

    float acc[4][4] = {};

    // Preload tile 0 into buffer 0
    {
        float4 av = *(const float4*)&A[(by*64 + ar)*DMODEL + k0 + ak4*4];
        float4 bv = *(const float4*)&W[(k0 + bk_)*DMODEL + bx*64 + bn4*4];
        *(float4*)&As[0][ar*20 + ak4*4] = av;
        *(float4*)&Bs[0][bk_*64 + bn4*4] = bv;
    }
    __syncthreads();

    #pragma unroll
    for (int it = 0; it < KCHUNK/16; it++) {
        const int buf = it & 1;
        float4 av, bv;
        if (it < KCHUNK/16 - 1) {
            const int kb = k0 + (it+1)*16;
            av = *(const float4*)&A[(by*64 + ar)*DMODEL + kb + ak4*4];
            bv = *(const float4*)&W[(kb + bk_)*DMODEL + bx*64 + bn4*4];
        }
        #pragma unroll
        for (int k = 0; k < 16; k++) {
            float4 b = *(const float4*)&Bs[buf][k*64 + tx*4];
            float a0 = As[buf][(ty*4+0)*20 + k];
            float a1 = As[buf][(ty*4+1)*20 + k];
            float a2 = As[buf][(ty*4+2)*20 + k];
            float a3 = As[buf][(ty*4+3)*20 + k];
            acc[0][0] += a0*b.x; acc[0][1] += a0*b.y; acc[0][2] += a0*b.z; acc[0][3] += a0*b.w;
            acc[1][0] += a1*b.x; acc[1][1] += a1*b.y; acc[1][2] += a1*b.z; acc[1][3] += a1*b.w;
            acc[2][0] += a2*b.x; acc[2][1] += a2*b.y; acc[2][2] += a2*b.z; acc[2][3] += a2*b.w;
            acc[3][0] += a3*b.x; acc[3][1] += a3*b.y; acc[3][2] += a3*b.z; acc[3][3] += a3*b.w;
        }
        if (it < KCHUNK/16 - 1) {
            *(float4*)&As[buf^1][ar*20 + ak4*4] = av;
            *(float4*)&Bs[buf^1][bk_*64 + bn4*4] = bv;
        }
        __syncthreads();
    }

    float* P = &g_part[(size_t)kz * NROWS * DMODEL];
    #pragma unroll
    for (int rr = 0; rr < 4; rr++)
        *(float4*)&P[(r0+rr)*DMODEL + c0] = make_float4(acc[rr][0], acc[rr][1], acc[rr][2], acc[rr][3]);
}

// ---------------------------------------------------------------------------
// Attention per row: reduce qk partials (+bqk) -> scores -> softmax -> wp
// ---------------------------------------------------------------------------
__global__ __launch_bounds__(256) void attn_kernel(const float* __restrict__ pair)
{
    extern __shared__ float sm[];
    float* pairS = sm;                       // 256*68
    float* qk_sm = sm + 256*PSTR;            // 512
    float* w_sm  = qk_sm + DMODEL;           // 2048
    float* red   = w_sm + 2048;              // 8192

    const int row  = blockIdx.x;
    const int tid  = threadIdx.x;
    const int lane = tid & 31;
    const int warp = tid >> 5;

    // Load pair row tile (256 x 64) into padded SMEM
    const float4* pg = (const float4*)(pair + (size_t)row * (LSEQ*CB));
    #pragma unroll
    for (int it = 0; it < 16; it++) {
        int f = tid + it*256;
        int j = f >> 4, c4 = f & 15;
        float4 v = pg[f];
        *(float4*)&pairS[j*PSTR + c4*4] = v;
    }
    // Reduce split-K partials for this row's qk vector
    {
        float2 acc = *(const float2*)&g_bqk[tid*2];
        #pragma unroll
        for (int kz = 0; kz < KSPLIT; kz++) {
            float2 v = *(const float2*)&g_part[((size_t)kz*NROWS + row)*DMODEL + tid*2];
            acc.x += v.x; acc.y += v.y;
        }
        *(float2*)&qk_sm[tid*2] = acc;
    }
    __syncthreads();

    // Scores for this thread's j across all heads
    float s[NHEAD] = {};
    {
        const float4* prow = (const float4*)&pairS[tid*PSTR];
        #pragma unroll
        for (int c4 = 0; c4 < 16; c4++) {
            float4 p = prow[c4];
            #pragma unroll
            for (int h = 0; h < NHEAD; h++) {
                float4 q = *(const float4*)&qk_sm[h*64 + c4*4];
                s[h] += p.x*q.x + p.y*q.y + p.z*q.z + p.w*q.w;
            }
        }
    }

    // Softmax over j (per head)
    #pragma unroll
    for (int h = 0; h < NHEAD; h++) {
        float v = s[h];
        #pragma unroll
        for (int o = 16; o; o >>= 1) v = fmaxf(v, __shfl_xor_sync(0xffffffffu, v, o));
        if (lane == 0) red[warp*NHEAD + h] = v;
    }
    __syncthreads();
    float m[NHEAD];
    #pragma unroll
    for (int h = 0; h < NHEAD; h++) {
        float v = red[h];
        #pragma unroll
        for (int w2 = 1; w2 < 8; w2++) v = fmaxf(v, red[w2*NHEAD + h]);
        m[h] = v;
    }
    __syncthreads();

    float e[NHEAD], Zi[NHEAD];
    #pragma unroll
    for (int h = 0; h < NHEAD; h++) {
        e[h] = __expf(s[h] - m[h]);
        float v = e[h];
        #pragma unroll
        for (int o = 16; o; o >>= 1) v += __shfl_xor_sync(0xffffffffu, v, o);
        if (lane == 0) red[warp*NHEAD + h] = v;
    }
    __syncthreads();
    #pragma unroll
    for (int h = 0; h < NHEAD; h++) {
        float v = 0.f;
        #pragma unroll
        for (int w2 = 0; w2 < 8; w2++) v += red[w2*NHEAD + h];
        Zi[h] = 1.0f / v;
    }
    __syncthreads();

    // Store normalized weights transposed: w_sm[j][h]
    {
        float4 wlo = make_float4(e[0]*Zi[0], e[1]*Zi[1], e[2]*Zi[2], e[3]*Zi[3]);
        float4 whi = make_float4(e[4]*Zi[4], e[5]*Zi[5], e[6]*Zi[6], e[7]*Zi[7]);
        *(float4*)&w_sm[tid*8 + 0] = wlo;
        *(float4*)&w_sm[tid*8 + 4] = whi;
    }
    __syncthreads();

    // wp partials: thread = (c4, jgroup); all 8 heads in registers
    {
        const int c4 = tid & 15, jg = tid >> 4;
        float4 acc[NHEAD];
        #pragma unroll
        for (int h = 0; h < NHEAD; h++) acc[h] = make_float4(0.f,0.f,0.f,0.f);
        #pragma unroll 4
        for (int jj = 0; jj < 16; jj++) {
            int j = jg*16 + jj;
            float4 p  = *(const float4*)&pairS[j*PSTR + c4*4];
            float4 wA = *(const float4*)&w_sm[j*8];
            float4 wB = *(const float4*)&w_sm[j*8 + 4];
            acc[0].x += wA.x*p.x; acc[0].y += wA.x*p.y; acc[0].z += wA.x*p.z; acc[0].w += wA.x*p.w;
            acc[1].x += wA.y*p.x; acc[1].y += wA.y*p.y; acc[1].z += wA.y*p.z; acc[1].w += wA.y*p.w;
            acc[2].x += wA.z*p.x; acc[2].y += wA.z*p.y; acc[2].z += wA.z*p.z; acc[2].w += wA.z*p.w;
            acc[3].x += wA.w*p.x; acc[3].y += wA.w*p.y; acc[3].z += wA.w*p.z; acc[3].w += wA.w*p.w;
            acc[4].x += wB.x*p.x; acc[4].y += wB.x*p.y; acc[4].z += wB.x*p.z; acc[4].w += wB.x*p.w;
            acc[5].x += wB.y*p.x; acc[5].y += wB.y*p.y; acc[5].z += wB.y*p.z; acc[5].w += wB.y*p.w;
            acc[6].x += wB.z*p.x; acc[6].y += wB.z*p.y; acc[6].z += wB.z*p.z; acc[6].w += wB.z*p.w;
            acc[7].x += wB.w*p.x; acc[7].y += wB.w*p.y; acc[7].z += wB.w*p.z; acc[7].w += wB.w*p.w;
        }
        #pragma unroll
        for (int h = 0; h < NHEAD; h++)
            *(float4*)&red[((jg*NHEAD + h)*16 + c4)*4] = acc[h];
    }
    __syncthreads();

    // Final reduce over 16 jgroups -> g_wp
    if (tid < 128) {
        const int h = tid >> 4, c4 = tid & 15;
        float4 sum = make_float4(0.f,0.f,0.f,0.f);
        #pragma unroll
        for (int jg = 0; jg < 16; jg++) {
            float4 v = *(const float4*)&red[((jg*NHEAD + h)*16 + c4)*4];
            sum.x += v.x; sum.y += v.y; sum.z += v.z; sum.w += v.w;
        }
        *(float4*)&g_wp[row*DMODEL + h*64 + c4*4] = sum;
    }
}

// ---------------------------------------------------------------------------
// LayerNorm(sum_kz part + bvo + x) * gamma + beta -> out.
// ---------------------------------------------------------------------------
__global__ __launch_bounds__(128) void ln_kernel(
    const float* __restrict__ x, const float* __restrict__ gamma,
    const float* __restrict__ beta, float* __restrict__ out)
{
    __shared__ float rs[8];
    const int row = blockIdx.x;
    const int tid = threadIdx.x;
    const int lane = tid & 31, warp = tid >> 5;

    float4 x4 = *(const float4*)&x[row*DMODEL + tid*4];
    float4 b4v = *(const float4*)&g_bvo[tid*4];
    float y0 = x4.x + b4v.x, y1 = x4.y + b4v.y, y2 = x4.z + b4v.z, y3 = x4.w + b4v.w;
    #pragma unroll
    for (int kz = 0; kz < KSPLIT; kz++) {
        float4 p4 = *(const float4*)&g_part[((size_t)kz*NROWS + row)*DMODEL + tid*4];
        y0 += p4.x; y1 += p4.y; y2 += p4.z; y3 += p4.w;
    }

    float sum = y0 + y1 + y2 + y3;
    float sq  = y0*y0 + y1*y1 + y2*y2 + y3*y3;
    #pragma unroll
    for (int o = 16; o; o >>= 1) {
        sum += __shfl_xor_sync(0xffffffffu, sum, o);
        sq  += __shfl_xor_sync(0xffffffffu, sq,  o);
    }
    if (lane == 0) { rs[warp] = sum; rs[4 + warp] = sq; }
    __syncthreads();
    float ts = rs[0] + rs[1] + rs[2] + rs[3];
    float tq = rs[4] + rs[5] + rs[6] + rs[7];
    float mu  = ts * (1.0f/DMODEL);
    float var = tq * (1.0f/DMODEL) - mu*mu;
    float r = rsqrtf(var + 1e-5f);

    float4 g4 = *(const float4*)&gamma[tid*4];
    float4 b4 = *(const float4*)&beta[tid*4];
    float4 o_;
    o_.x = (y0 - mu)*r*g4.x + b4.x;
    o_.y = (y1 - mu)*r*g4.y + b4.y;
    o_.z = (y2 - mu)*r*g4.z + b4.z;
    o_.w = (y3 - mu)*r*g4.w + b4.w;
    *(float4*)&out[row*DMODEL + tid*4] = o_;
}

// ---------------------------------------------------------------------------
extern "C" void kernel_launch(void* const* d_in, const int* in_sizes, int n_in,
                              void* d_out, int out_size)
{
    const float* x     = (const float*)d_in[0];
    const float* pair  = (const float*)d_in[1];
    const float* Wq    = (const float*)d_in[2];
    const float* bq    = (const float*)d_in[3];
    const float* Wk    = (const float*)d_in[4];
    // bk (d_in[5]) is softmax-invariant (per-(row,h) constant), dropped
    const float* Wv    = (const float*)d_in[6];
    const float* bv    = (const float*)d_in[7];
    const float* Wo    = (const float*)d_in[8];
    const float* bo    = (const float*)d_in[9];
    const float* gamma = (const float*)d_in[10];
    const float* beta  = (const float*)d_in[11];
    float* out = (float*)d_out;

    float *pWP, *pWqk, *pWvo;
    cudaGetSymbolAddress((void**)&pWP,  g_wp);
    cudaGetSymbolAddress((void**)&pWqk, g_Wqk);
    cudaGetSymbolAddress((void**)&pWvo, g_Wvo);

    const int ATTN_SMEM = (256*PSTR + DMODEL + 2048 + 8192) * 4;  // 112640 B
    cudaFuncSetAttribute(attn_kernel, cudaFuncAttributeMaxDynamicSharedMemorySize, ATTN_SMEM);

    dim3 ggrid(DMODEL/64, NROWS/64, KSPLIT);   // (8,8,8) = 512 blocks

    prep_kernel<<<136, 256>>>(Wq, bq, Wk, Wv, bv, Wo, bo);
    gemm_splitk_kernel<<<ggrid, 256>>>(x, pWqk);            // qk partials
    attn_kernel<<<NROWS, 256, ATTN_SMEM>>>(pair);           // reduce + softmax + wp
    gemm_splitk_kernel<<<ggrid, 256>>>(pWP, pWvo);          // o partials
    ln_kernel<<<NROWS, 128>>>(x, gamma, beta, out);         // reduce + LN(o + x)
}

// round 7
// speedup vs baseline: 1.8800x; 1.0013x over previous
#include <cuda_runtime.h>
#include <math.h>

#define BATCH 2
#define LSEQ 256
#define CB 64
#define DMODEL 512
#define NHEAD 8
#define HD 64
#define NROWS (BATCH*LSEQ)   // 512
#define PSTR 68              // padded pair row stride (floats)
#define WSTR 12              // padded w_sm row stride (floats)
#define KSPLIT 16
#define KCHUNK (DMODEL/KSPLIT)   // 32

// Static scratch
__device__ float g_part[KSPLIT*NROWS*DMODEL];   // split-K partials (reused by both GEMMs)
__device__ float g_wp[NROWS*DMODEL];
__device__ float g_Wqk[DMODEL*DMODEL];
__device__ float g_bqk[DMODEL];
__device__ float g_Wvo[DMODEL*DMODEL];
__device__ float g_bvo[DMODEL];

// ---------------------------------------------------------------------------
// Prep: build combined weights (tiny GEMMs, ~34 MFLOP total).
// ---------------------------------------------------------------------------
__global__ __launch_bounds__(256) void prep_kernel(
    const float* __restrict__ Wq, const float* __restrict__ bq,
    const float* __restrict__ Wk,
    const float* __restrict__ Wv, const float* __restrict__ bv,
    const float* __restrict__ Wo, const float* __restrict__ bo)
{
    __shared__ float Asm[64*68];
    __shared__ float Bsm[64*68];
    const int bid = blockIdx.x;
    const int tid = threadIdx.x;
    const int tx = tid & 15;
    const int ty = tid >> 4;

    if (bid < 64) {
        const int h = bid >> 3, et = bid & 7, e0 = et * 64;
        #pragma unroll
        for (int p = 0; p < 4; p++) {
            int f = tid + p*256; int e = f >> 4, d4 = f & 15;
            float4 v = *(const float4*)&Wq[(e0+e)*DMODEL + h*64 + d4*4];
            *(float4*)&Asm[e*68 + d4*4] = v;
        }
        #pragma unroll
        for (int p = 0; p < 4; p++) {
            int f = tid + p*256; int c = f >> 4, d4 = f & 15;
            float4 v = *(const float4*)&Wk[c*DMODEL + h*64 + d4*4];
            Bsm[(d4*4+0)*68 + c] = v.x; Bsm[(d4*4+1)*68 + c] = v.y;
            Bsm[(d4*4+2)*68 + c] = v.z; Bsm[(d4*4+3)*68 + c] = v.w;
        }
        __syncthreads();
        float acc[4][4] = {};
        #pragma unroll 8
        for (int d = 0; d < 64; d++) {
            float4 b = *(const float4*)&Bsm[d*68 + tx*4];
            #pragma unroll
            for (int rr = 0; rr < 4; rr++) {
                float a = Asm[(ty*4+rr)*68 + d];
                acc[rr][0] += a*b.x; acc[rr][1] += a*b.y;
                acc[rr][2] += a*b.z; acc[rr][3] += a*b.w;
            }
        }
        #pragma unroll
        for (int rr = 0; rr < 4; rr++) {
            float4 o;
            o.x = acc[rr][0]*0.125f; o.y = acc[rr][1]*0.125f;
            o.z = acc[rr][2]*0.125f; o.w = acc[rr][3]*0.125f;
            *(float4*)&g_Wqk[(e0 + ty*4+rr)*DMODEL + h*64 + tx*4] = o;
        }
        if (et == 0 && tid < 64) {
            float acc2 = 0.f;
            #pragma unroll 8
            for (int d = 0; d < 64; d++) acc2 += bq[h*64+d] * Bsm[d*68 + tid];
            g_bqk[h*64 + tid] = acc2 * 0.125f;
        }
    } else if (bid < 128) {
        const int b2 = bid - 64, h = b2 >> 3, nt = b2 & 7, n0 = nt * 64;
        #pragma unroll
        for (int p = 0; p < 4; p++) {
            int f = tid + p*256; int c = f >> 4, d4 = f & 15;
            float4 v = *(const float4*)&Wv[c*DMODEL + h*64 + d4*4];
            *(float4*)&Asm[c*68 + d4*4] = v;
        }
        #pragma unroll
        for (int p = 0; p < 4; p++) {
            int f = tid + p*256; int d = f >> 4, n4 = f & 15;
            float4 v = *(const float4*)&Wo[(h*64+d)*DMODEL + n0 + n4*4];
            *(float4*)&Bsm[d*68 + n4*4] = v;
        }
        __syncthreads();
        float acc[4][4] = {};
        #pragma unroll 8
        for (int d = 0; d < 64; d++) {
            float4 b = *(const float4*)&Bsm[d*68 + tx*4];
            #pragma unroll
            for (int rr = 0; rr < 4; rr++) {
                float a = Asm[(ty*4+rr)*68 + d];
                acc[rr][0] += a*b.x; acc[rr][1] += a*b.y;
                acc[rr][2] += a*b.z; acc[rr][3] += a*b.w;
            }
        }
        #pragma unroll
        for (int rr = 0; rr < 4; rr++) {
            float4 o;
            o.x = acc[rr][0]; o.y = acc[rr][1]; o.z = acc[rr][2]; o.w = acc[rr][3];
            *(float4*)&g_Wvo[(h*64 + ty*4+rr)*DMODEL + n0 + tx*4] = o;
        }
    } else {
        const int nb = bid - 128, n0 = nb * 64;
        const int n = tid & 63, mg = tid >> 6;
        float acc = 0.f;
        for (int m = mg*128; m < mg*128 + 128; m++)
            acc += bv[m] * Wo[m*DMODEL + n0 + n];
        Asm[mg*64 + n] = acc;
        __syncthreads();
        if (tid < 64) {
            float s = Asm[tid] + Asm[64+tid] + Asm[128+tid] + Asm[192+tid] + bo[n0+tid];
            g_bvo[n0 + tid] = s;
        }
    }
}

// ---------------------------------------------------------------------------
// Split-K GEMM: partial[kz] = A[:, kz*32:(kz+1)*32] @ W[chunk]
// BM=64, BN=64, KCHUNK=32; 128 threads; 8x4/thread; grid (8,8,16)=1024 blocks.
// Whole K-chunk staged once (single __syncthreads), A stored transposed so
// the 8-row fragment is two LDS128.
// ---------------------------------------------------------------------------
__global__ __launch_bounds__(128) void gemm_splitk_kernel(
    const float* __restrict__ A, const float* __restrict__ W)
{
    __shared__ float As[32*68];   // [k][m], padded
    __shared__ float Bs[32*64];   // [k][n]
    const int bx = blockIdx.x;    // n tile (64)
    const int by = blockIdx.y;    // m tile (64)
    const int kz = blockIdx.z;
    const int tid = threadIdx.x;
    const int tx = tid & 15;      // 4 cols
    const int ty = tid >> 4;      // 8 rows (8 groups)
    const int k0 = kz * KCHUNK;

    // Load A chunk 64x32, store transposed As[k][m]
    {
        const int am = tid >> 3;     // 0..15
        const int ak4 = tid & 7;     // 0..7  (k = ak4*4 .. +3)
        #pragma unroll
        for (int p = 0; p < 4; p++) {
            int m = am + p*16;
            float4 v = *(const float4*)&A[(by*64 + m)*DMODEL + k0 + ak4*4];
            As[(ak4*4+0)*68 + m] = v.x;
            As[(ak4*4+1)*68 + m] = v.y;
            As[(ak4*4+2)*68 + m] = v.z;
            As[(ak4*4+3)*68 + m] = v.w;
        }
    }
    // Load B chunk 32x64
    {
        const int bk = tid >> 4;     // 0..7
        const int bn4 = tid & 15;
        #pragma unroll
        for (int p = 0; p < 4; p++) {
            int k = bk + p*8;
            float4 v = *(const float4*)&W[(k0 + k)*DMODEL + bx*64 + bn4*4];
            *(float4*)&Bs[k*64 + bn4*4] = v;
        }
    }
    __syncthreads();

    float acc[8][4] = {};
    #pragma unroll 16
    for (int k = 0; k < KCHUNK; k++) {
        float4 b  = *(const float4*)&Bs[k*64 + tx*4];
        float4 a0 = *(const float4*)&As[k*68 + ty*8];
        float4 a1 = *(const float4*)&As[k*68 + ty*8 + 4];
        acc[0][0] += a0.x*b.x; acc[0][1] += a0.x*b.y; acc[0][2] += a0.x*b.z; acc[0][3] += a0.x*b.w;
        acc[1][0] += a0.y*b.x; acc[1][1] += a0.y*b.y; acc[1][2] += a0.y*b.z; acc[1][3] += a0.y*b.w;
        acc[2][0] += a0.z*b.x; acc[2][1] += a0.z*b.y; acc[2][2] += a0.z*b.z; acc[2][3] += a0.z*b.w;
        acc[3][0] += a0.w*b.x; acc[3][1] += a0.w*b.y; acc[3][2] += a0.w*b.z; acc[3][3] += a0.w*b.w;
        acc[4][0] += a1.x*b.x; acc[4][1] += a1.x*b.y; acc[4][2] += a1.x*b.z; acc[4][3] += a1.x*b.w;
        acc[5][0] += a1.y*b.x; acc[5][1] += a1.y*b.y; acc[5][2] += a1.y*b.z; acc[5][3] += a1.y*b.w;
        acc[6][0] += a1.z*b.x; acc[6][1] += a1.z*b.y; acc[6][2] += a1.z*b.z; acc[6][3] += a1.z*b.w;
        acc[7][0] += a1.w*b.x; acc[7][1] += a1.w*b.y; acc[7][2] += a1.w*b.z; acc[7][3] += a1.w*b.w;
    }

    float* P = &g_part[(size_t)kz * NROWS * DMODEL];
    const int r0 = by*64 + ty*8;
    const int c0 = bx*64 + tx*4;
    #pragma unroll
    for (int rr = 0; rr < 8; rr++)
        *(float4*)&P[(r0+rr)*DMODEL + c0] = make_float4(acc[rr][0], acc[rr][1], acc[rr][2], acc[rr][3]);
}

// ---------------------------------------------------------------------------
// Attention per row: reduce qk partials (+bqk) -> scores -> softmax -> wp
// ---------------------------------------------------------------------------
__global__ __launch_bounds__(256) void attn_kernel(const float* __restrict__ pair)
{
    extern __shared__ float sm[];
    float* pairS = sm;                       // 256*68  = 17408 f
    float* qk_sm = sm + 256*PSTR;            // 512 f
    float* w_sm  = qk_sm + DMODEL;           // 256*12 = 3072 f  ([j][h], pad 12)
    float* red   = w_sm + 256*WSTR;          // 8*8*64 = 4096 f  (wp partials / softmax red)

    const int row  = blockIdx.x;
    const int tid  = threadIdx.x;
    const int lane = tid & 31;
    const int warp = tid >> 5;

    // Load pair row tile (256 x 64) into padded SMEM
    const float4* pg = (const float4*)(pair + (size_t)row * (LSEQ*CB));
    #pragma unroll
    for (int it = 0; it < 16; it++) {
        int f = tid + it*256;
        int j = f >> 4, c4 = f & 15;
        float4 v = pg[f];
        *(float4*)&pairS[j*PSTR + c4*4] = v;
    }
    // Reduce split-K partials for this row's qk vector
    {
        float2 acc = *(const float2*)&g_bqk[tid*2];
        #pragma unroll
        for (int kz = 0; kz < KSPLIT; kz++) {
            float2 v = *(const float2*)&g_part[((size_t)kz*NROWS + row)*DMODEL + tid*2];
            acc.x += v.x; acc.y += v.y;
        }
        *(float2*)&qk_sm[tid*2] = acc;
    }
    __syncthreads();

    // Scores for this thread's j across all heads
    float s[NHEAD] = {};
    {
        const float4* prow = (const float4*)&pairS[tid*PSTR];
        #pragma unroll
        for (int c4 = 0; c4 < 16; c4++) {
            float4 p = prow[c4];
            #pragma unroll
            for (int h = 0; h < NHEAD; h++) {
                float4 q = *(const float4*)&qk_sm[h*64 + c4*4];
                s[h] += p.x*q.x + p.y*q.y + p.z*q.z + p.w*q.w;
            }
        }
    }

    // Softmax over j (per head)
    #pragma unroll
    for (int h = 0; h < NHEAD; h++) {
        float v = s[h];
        #pragma unroll
        for (int o = 16; o; o >>= 1) v = fmaxf(v, __shfl_xor_sync(0xffffffffu, v, o));
        if (lane == 0) red[warp*NHEAD + h] = v;
    }
    __syncthreads();
    float m[NHEAD];
    #pragma unroll
    for (int h = 0; h < NHEAD; h++) {
        float v = red[h];
        #pragma unroll
        for (int w2 = 1; w2 < 8; w2++) v = fmaxf(v, red[w2*NHEAD + h]);
        m[h] = v;
    }
    __syncthreads();

    float e[NHEAD], Zi[NHEAD];
    #pragma unroll
    for (int h = 0; h < NHEAD; h++) {
        e[h] = __expf(s[h] - m[h]);
        float v = e[h];
        #pragma unroll
        for (int o = 16; o; o >>= 1) v += __shfl_xor_sync(0xffffffffu, v, o);
        if (lane == 0) red[warp*NHEAD + h] = v;
    }
    __syncthreads();
    #pragma unroll
    for (int h = 0; h < NHEAD; h++) {
        float v = 0.f;
        #pragma unroll
        for (int w2 = 0; w2 < 8; w2++) v += red[w2*NHEAD + h];
        Zi[h] = 1.0f / v;
    }
    __syncthreads();

    // Store normalized weights: w_sm[j][h0..7], stride WSTR
    {
        float4 wlo = make_float4(e[0]*Zi[0], e[1]*Zi[1], e[2]*Zi[2], e[3]*Zi[3]);
        float4 whi = make_float4(e[4]*Zi[4], e[5]*Zi[5], e[6]*Zi[6], e[7]*Zi[7]);
        *(float4*)&w_sm[tid*WSTR + 0] = wlo;
        *(float4*)&w_sm[tid*WSTR + 4] = whi;
    }
    __syncthreads();

    // wp partials: thread = (jg = tid&15, c4 = tid>>4); all 8 heads in regs.
    // j rotated per-jg to avoid bank conflicts on pairS.
    {
        const int jg = tid & 15, c4 = tid >> 4;
        float4 acc[NHEAD];
        #pragma unroll
        for (int h = 0; h < NHEAD; h++) acc[h] = make_float4(0.f,0.f,0.f,0.f);
        #pragma unroll 4
        for (int jj = 0; jj < 16; jj++) {
            int j = jg*16 + ((jj + jg) & 15);
            float4 p  = *(const float4*)&pairS[j*PSTR + c4*4];
            float4 wA = *(const float4*)&w_sm[j*WSTR];
            float4 wB = *(const float4*)&w_sm[j*WSTR + 4];
            acc[0].x += wA.x*p.x; acc[0].y += wA.x*p.y; acc[0].z += wA.x*p.z; acc[0].w += wA.x*p.w;
            acc[1].x += wA.y*p.x; acc[1].y += wA.y*p.y; acc[1].z += wA.y*p.z; acc[1].w += wA.y*p.w;
            acc[2].x += wA.z*p.x; acc[2].y += wA.z*p.y; acc[2].z += wA.z*p.z; acc[2].w += wA.z*p.w;
            acc[3].x += wA.w*p.x; acc[3].y += wA.w*p.y; acc[3].z += wA.w*p.z; acc[3].w += wA.w*p.w;
            acc[4].x += wB.x*p.x; acc[4].y += wB.x*p.y; acc[4].z += wB.x*p.z; acc[4].w += wB.x*p.w;
            acc[5].x += wB.y*p.x; acc[5].y += wB.y*p.y; acc[5].z += wB.y*p.z; acc[5].w += wB.y*p.w;
            acc[6].x += wB.z*p.x; acc[6].y += wB.z*p.y; acc[6].z += wB.z*p.z; acc[6].w += wB.z*p.w;
            acc[7].x += wB.w*p.x; acc[7].y += wB.w*p.y; acc[7].z += wB.w*p.z; acc[7].w += wB.w*p.w;
        }
        // In-warp pre-reduction over jg distance 8 (lane ^ 8)
        #pragma unroll
        for (int h = 0; h < NHEAD; h++) {
            acc[h].x += __shfl_xor_sync(0xffffffffu, acc[h].x, 8);
            acc[h].y += __shfl_xor_sync(0xffffffffu, acc[h].y, 8);
            acc[h].z += __shfl_xor_sync(0xffffffffu, acc[h].z, 8);
            acc[h].w += __shfl_xor_sync(0xffffffffu, acc[h].w, 8);
        }
        if (jg < 8) {
            #pragma unroll
            for (int h = 0; h < NHEAD; h++)
                *(float4*)&red[(jg*NHEAD + h)*64 + c4*4] = acc[h];
        }
    }
    __syncthreads();

    // Final reduce over 8 jgroups -> g_wp
    if (tid < 128) {
        const int h = tid >> 4, c4 = tid & 15;
        float4 sum = make_float4(0.f,0.f,0.f,0.f);
        #pragma unroll
        for (int jg = 0; jg < 8; jg++) {
            float4 v = *(const float4*)&red[(jg*NHEAD + h)*64 + c4*4];
            sum.x += v.x; sum.y += v.y; sum.z += v.z; sum.w += v.w;
        }
        *(float4*)&g_wp[row*DMODEL + h*64 + c4*4] = sum;
    }
}

// ---------------------------------------------------------------------------
// LayerNorm(sum_kz part + bvo + x) * gamma + beta -> out.
// ---------------------------------------------------------------------------
__global__ __launch_bounds__(128) void ln_kernel(
    const float* __restrict__ x, const float* __restrict__ gamma,
    const float* __restrict__ beta, float* __restrict__ out)
{
    __shared__ float rs[8];
    const int row = blockIdx.x;
    const int tid = threadIdx.x;
    const int lane = tid & 31, warp = tid >> 5;

    float4 x4 = *(const float4*)&x[row*DMODEL + tid*4];
    float4 b4v = *(const float4*)&g_bvo[tid*4];
    float y0 = x4.x + b4v.x, y1 = x4.y + b4v.y, y2 = x4.z + b4v.z, y3 = x4.w + b4v.w;
    #pragma unroll
    for (int kz = 0; kz < KSPLIT; kz++) {
        float4 p4 = *(const float4*)&g_part[((size_t)kz*NROWS + row)*DMODEL + tid*4];
        y0 += p4.x; y1 += p4.y; y2 += p4.z; y3 += p4.w;
    }

    float sum = y0 + y1 + y2 + y3;
    float sq  = y0*y0 + y1*y1 + y2*y2 + y3*y3;
    #pragma unroll
    for (int o = 16; o; o >>= 1) {
        sum += __shfl_xor_sync(0xffffffffu, sum, o);
        sq  += __shfl_xor_sync(0xffffffffu, sq,  o);
    }
    if (lane == 0) { rs[warp] = sum; rs[4 + warp] = sq; }
    __syncthreads();
    float ts = rs[0] + rs[1] + rs[2] + rs[3];
    float tq = rs[4] + rs[5] + rs[6] + rs[7];
    float mu  = ts * (1.0f/DMODEL);
    float var = tq * (1.0f/DMODEL) - mu*mu;
    float r = rsqrtf(var + 1e-5f);

    float4 g4 = *(const float4*)&gamma[tid*4];
    float4 b4 = *(const float4*)&beta[tid*4];
    float4 o_;
    o_.x = (y0 - mu)*r*g4.x + b4.x;
    o_.y = (y1 - mu)*r*g4.y + b4.y;
    o_.z = (y2 - mu)*r*g4.z + b4.z;
    o_.w = (y3 - mu)*r*g4.w + b4.w;
    *(float4*)&out[row*DMODEL + tid*4] = o_;
}

// ---------------------------------------------------------------------------
extern "C" void kernel_launch(void* const* d_in, const int* in_sizes, int n_in,
                              void* d_out, int out_size)
{
    const float* x     = (const float*)d_in[0];
    const float* pair  = (const float*)d_in[1];
    const float* Wq    = (const float*)d_in[2];
    const float* bq    = (const float*)d_in[3];
    const float* Wk    = (const float*)d_in[4];
    // bk (d_in[5]) is softmax-invariant (per-(row,h) constant), dropped
    const float* Wv    = (const float*)d_in[6];
    const float* bv    = (const float*)d_in[7];
    const float* Wo    = (const float*)d_in[8];
    const float* bo    = (const float*)d_in[9];
    const float* gamma = (const float*)d_in[10];
    const float* beta  = (const float*)d_in[11];
    float* out = (float*)d_out;

    float *pWP, *pWqk, *pWvo;
    cudaGetSymbolAddress((void**)&pWP,  g_wp);
    cudaGetSymbolAddress((void**)&pWqk, g_Wqk);
    cudaGetSymbolAddress((void**)&pWvo, g_Wvo);

    const int ATTN_SMEM = (256*PSTR + DMODEL + 256*WSTR + 8*NHEAD*64) * 4;  // 100352 B
    cudaFuncSetAttribute(attn_kernel, cudaFuncAttributeMaxDynamicSharedMemorySize, ATTN_SMEM);

    dim3 ggrid(DMODEL/64, NROWS/64, KSPLIT);   // (8,8,16) = 1024 blocks

    prep_kernel<<<136, 256>>>(Wq, bq, Wk, Wv, bv, Wo, bo);
    gemm_splitk_kernel<<<ggrid, 128>>>(x, pWqk);            // qk partials
    attn_kernel<<<NROWS, 256, ATTN_SMEM>>>(pair);           // reduce + softmax + wp
    gemm_splitk_kernel<<<ggrid, 128>>>(pWP, pWvo);          // o partials
    ln_kernel<<<NROWS, 128>>>(x, gamma, beta, out);         // reduce + LN(o + x)
}

// round 8
// speedup vs baseline: 1.9583x; 1.0417x over previous
#include <cuda_runtime.h>
#include <math.h>

#define BATCH 2
#define LSEQ 256
#define CB 64
#define DMODEL 512
#define NHEAD 8
#define HD 64
#define NROWS (BATCH*LSEQ)   // 512
#define PSTR 68              // padded pair row stride (floats)
#define KSPLIT 16
#define KCHUNK (DMODEL/KSPLIT)   // 32

// Static scratch
__device__ float g_part[KSPLIT*NROWS*DMODEL];   // split-K partials (reused by both GEMMs)
__device__ float g_wp[NROWS*DMODEL];
__device__ float g_Wqk[DMODEL*DMODEL];
__device__ float g_bqk[DMODEL];
__device__ float g_Wvo[DMODEL*DMODEL];
__device__ float g_bvo[DMODEL];

// ---------------------------------------------------------------------------
// Prep: build combined weights (tiny GEMMs, ~34 MFLOP total).
// ---------------------------------------------------------------------------
__global__ __launch_bounds__(256) void prep_kernel(
    const float* __restrict__ Wq, const float* __restrict__ bq,
    const float* __restrict__ Wk,
    const float* __restrict__ Wv, const float* __restrict__ bv,
    const float* __restrict__ Wo, const float* __restrict__ bo)
{
    __shared__ float Asm[64*68];
    __shared__ float Bsm[64*68];
    const int bid = blockIdx.x;
    const int tid = threadIdx.x;
    const int tx = tid & 15;
    const int ty = tid >> 4;

    if (bid < 64) {
        const int h = bid >> 3, et = bid & 7, e0 = et * 64;
        #pragma unroll
        for (int p = 0; p < 4; p++) {
            int f = tid + p*256; int e = f >> 4, d4 = f & 15;
            float4 v = *(const float4*)&Wq[(e0+e)*DMODEL + h*64 + d4*4];
            *(float4*)&Asm[e*68 + d4*4] = v;
        }
        #pragma unroll
        for (int p = 0; p < 4; p++) {
            int f = tid + p*256; int c = f >> 4, d4 = f & 15;
            float4 v = *(const float4*)&Wk[c*DMODEL + h*64 + d4*4];
            Bsm[(d4*4+0)*68 + c] = v.x; Bsm[(d4*4+1)*68 + c] = v.y;
            Bsm[(d4*4+2)*68 + c] = v.z; Bsm[(d4*4+3)*68 + c] = v.w;
        }
        __syncthreads();
        float acc[4][4] = {};
        #pragma unroll 8
        for (int d = 0; d < 64; d++) {
            float4 b = *(const float4*)&Bsm[d*68 + tx*4];
            #pragma unroll
            for (int rr = 0; rr < 4; rr++) {
                float a = Asm[(ty*4+rr)*68 + d];
                acc[rr][0] += a*b.x; acc[rr][1] += a*b.y;
                acc[rr][2] += a*b.z; acc[rr][3] += a*b.w;
            }
        }
        #pragma unroll
        for (int rr = 0; rr < 4; rr++) {
            float4 o;
            o.x = acc[rr][0]*0.125f; o.y = acc[rr][1]*0.125f;
            o.z = acc[rr][2]*0.125f; o.w = acc[rr][3]*0.125f;
            *(float4*)&g_Wqk[(e0 + ty*4+rr)*DMODEL + h*64 + tx*4] = o;
        }
        if (et == 0 && tid < 64) {
            float acc2 = 0.f;
            #pragma unroll 8
            for (int d = 0; d < 64; d++) acc2 += bq[h*64+d] * Bsm[d*68 + tid];
            g_bqk[h*64 + tid] = acc2 * 0.125f;
        }
    } else if (bid < 128) {
        const int b2 = bid - 64, h = b2 >> 3, nt = b2 & 7, n0 = nt * 64;
        #pragma unroll
        for (int p = 0; p < 4; p++) {
            int f = tid + p*256; int c = f >> 4, d4 = f & 15;
            float4 v = *(const float4*)&Wv[c*DMODEL + h*64 + d4*4];
            *(float4*)&Asm[c*68 + d4*4] = v;
        }
        #pragma unroll
        for (int p = 0; p < 4; p++) {
            int f = tid + p*256; int d = f >> 4, n4 = f & 15;
            float4 v = *(const float4*)&Wo[(h*64+d)*DMODEL + n0 + n4*4];
            *(float4*)&Bsm[d*68 + n4*4] = v;
        }
        __syncthreads();
        float acc[4][4] = {};
        #pragma unroll 8
        for (int d = 0; d < 64; d++) {
            float4 b = *(const float4*)&Bsm[d*68 + tx*4];
            #pragma unroll
            for (int rr = 0; rr < 4; rr++) {
                float a = Asm[(ty*4+rr)*68 + d];
                acc[rr][0] += a*b.x; acc[rr][1] += a*b.y;
                acc[rr][2] += a*b.z; acc[rr][3] += a*b.w;
            }
        }
        #pragma unroll
        for (int rr = 0; rr < 4; rr++) {
            float4 o;
            o.x = acc[rr][0]; o.y = acc[rr][1]; o.z = acc[rr][2]; o.w = acc[rr][3];
            *(float4*)&g_Wvo[(h*64 + ty*4+rr)*DMODEL + n0 + tx*4] = o;
        }
    } else {
        const int nb = bid - 128, n0 = nb * 64;
        const int n = tid & 63, mg = tid >> 6;
        float acc = 0.f;
        for (int m = mg*128; m < mg*128 + 128; m++)
            acc += bv[m] * Wo[m*DMODEL + n0 + n];
        Asm[mg*64 + n] = acc;
        __syncthreads();
        if (tid < 64) {
            float s = Asm[tid] + Asm[64+tid] + Asm[128+tid] + Asm[192+tid] + bo[n0+tid];
            g_bvo[n0 + tid] = s;
        }
    }
}

// ---------------------------------------------------------------------------
// Split-K GEMM: partial[kz] = A[:, kz*32:(kz+1)*32] @ W[chunk]
// BM=64, BN=64, KCHUNK=32; 128 threads; 8x4/thread; grid (8,8,16)=1024 blocks.
// Whole K-chunk staged once (single __syncthreads), A stored transposed.
// ---------------------------------------------------------------------------
__global__ __launch_bounds__(128) void gemm_splitk_kernel(
    const float* __restrict__ A, const float* __restrict__ W)
{
    __shared__ float As[32*68];   // [k][m], padded
    __shared__ float Bs[32*64];   // [k][n]
    const int bx = blockIdx.x;    // n tile (64)
    const int by = blockIdx.y;    // m tile (64)
    const int kz = blockIdx.z;
    const int tid = threadIdx.x;
    const int tx = tid & 15;      // 4 cols
    const int ty = tid >> 4;      // 8 rows (8 groups)
    const int k0 = kz * KCHUNK;

    // Load A chunk 64x32, store transposed As[k][m]
    {
        const int am = tid >> 3;     // 0..15
        const int ak4 = tid & 7;     // 0..7  (k = ak4*4 .. +3)
        #pragma unroll
        for (int p = 0; p < 4; p++) {
            int m = am + p*16;
            float4 v = *(const float4*)&A[(by*64 + m)*DMODEL + k0 + ak4*4];
            As[(ak4*4+0)*68 + m] = v.x;
            As[(ak4*4+1)*68 + m] = v.y;
            As[(ak4*4+2)*68 + m] = v.z;
            As[(ak4*4+3)*68 + m] = v.w;
        }
    }
    // Load B chunk 32x64
    {
        const int bk = tid >> 4;     // 0..7
        const int bn4 = tid & 15;
        #pragma unroll
        for (int p = 0; p < 4; p++) {
            int k = bk + p*8;
            float4 v = *(const float4*)&W[(k0 + k)*DMODEL + bx*64 + bn4*4];
            *(float4*)&Bs[k*64 + bn4*4] = v;
        }
    }
    __syncthreads();

    float acc[8][4] = {};
    #pragma unroll 16
    for (int k = 0; k < KCHUNK; k++) {
        float4 b  = *(const float4*)&Bs[k*64 + tx*4];
        float4 a0 = *(const float4*)&As[k*68 + ty*8];
        float4 a1 = *(const float4*)&As[k*68 + ty*8 + 4];
        acc[0][0] += a0.x*b.x; acc[0][1] += a0.x*b.y; acc[0][2] += a0.x*b.z; acc[0][3] += a0.x*b.w;
        acc[1][0] += a0.y*b.x; acc[1][1] += a0.y*b.y; acc[1][2] += a0.y*b.z; acc[1][3] += a0.y*b.w;
        acc[2][0] += a0.z*b.x; acc[2][1] += a0.z*b.y; acc[2][2] += a0.z*b.z; acc[2][3] += a0.z*b.w;
        acc[3][0] += a0.w*b.x; acc[3][1] += a0.w*b.y; acc[3][2] += a0.w*b.z; acc[3][3] += a0.w*b.w;
        acc[4][0] += a1.x*b.x; acc[4][1] += a1.x*b.y; acc[4][2] += a1.x*b.z; acc[4][3] += a1.x*b.w;
        acc[5][0] += a1.y*b.x; acc[5][1] += a1.y*b.y; acc[5][2] += a1.y*b.z; acc[5][3] += a1.y*b.w;
        acc[6][0] += a1.z*b.x; acc[6][1] += a1.z*b.y; acc[6][2] += a1.z*b.z; acc[6][3] += a1.z*b.w;
        acc[7][0] += a1.w*b.x; acc[7][1] += a1.w*b.y; acc[7][2] += a1.w*b.z; acc[7][3] += a1.w*b.w;
    }

    float* P = &g_part[(size_t)kz * NROWS * DMODEL];
    const int r0 = by*64 + ty*8;
    const int c0 = bx*64 + tx*4;
    #pragma unroll
    for (int rr = 0; rr < 8; rr++)
        *(float4*)&P[(r0+rr)*DMODEL + c0] = make_float4(acc[rr][0], acc[rr][1], acc[rr][2], acc[rr][3]);
}

// ---------------------------------------------------------------------------
// Attention per row: reduce qk partials (+bqk) -> scores -> softmax -> wp
// (wp structure = round-4 verified layout)
// ---------------------------------------------------------------------------
__global__ __launch_bounds__(256) void attn_kernel(const float* __restrict__ pair)
{
    extern __shared__ float sm[];
    float* pairS = sm;                       // 256*68
    float* qk_sm = sm + 256*PSTR;            // 512
    float* w_sm  = qk_sm + DMODEL;           // 2048 ([j][h])
    float* red   = w_sm + 2048;              // 8192

    const int row  = blockIdx.x;
    const int tid  = threadIdx.x;
    const int lane = tid & 31;
    const int warp = tid >> 5;

    // Load pair row tile (256 x 64) into padded SMEM
    const float4* pg = (const float4*)(pair + (size_t)row * (LSEQ*CB));
    #pragma unroll
    for (int it = 0; it < 16; it++) {
        int f = tid + it*256;
        int j = f >> 4, c4 = f & 15;
        float4 v = pg[f];
        *(float4*)&pairS[j*PSTR + c4*4] = v;
    }
    // Reduce split-K partials for this row's qk vector
    {
        float2 acc = *(const float2*)&g_bqk[tid*2];
        #pragma unroll
        for (int kz = 0; kz < KSPLIT; kz++) {
            float2 v = *(const float2*)&g_part[((size_t)kz*NROWS + row)*DMODEL + tid*2];
            acc.x += v.x; acc.y += v.y;
        }
        *(float2*)&qk_sm[tid*2] = acc;
    }
    __syncthreads();

    // Scores for this thread's j across all heads
    float s[NHEAD] = {};
    {
        const float4* prow = (const float4*)&pairS[tid*PSTR];
        #pragma unroll
        for (int c4 = 0; c4 < 16; c4++) {
            float4 p = prow[c4];
            #pragma unroll
            for (int h = 0; h < NHEAD; h++) {
                float4 q = *(const float4*)&qk_sm[h*64 + c4*4];
                s[h] += p.x*q.x + p.y*q.y + p.z*q.z + p.w*q.w;
            }
        }
    }

    // Softmax over j (per head)
    #pragma unroll
    for (int h = 0; h < NHEAD; h++) {
        float v = s[h];
        #pragma unroll
        for (int o = 16; o; o >>= 1) v = fmaxf(v, __shfl_xor_sync(0xffffffffu, v, o));
        if (lane == 0) red[warp*NHEAD + h] = v;
    }
    __syncthreads();
    float m[NHEAD];
    #pragma unroll
    for (int h = 0; h < NHEAD; h++) {
        float v = red[h];
        #pragma unroll
        for (int w2 = 1; w2 < 8; w2++) v = fmaxf(v, red[w2*NHEAD + h]);
        m[h] = v;
    }
    __syncthreads();

    float e[NHEAD], Zi[NHEAD];
    #pragma unroll
    for (int h = 0; h < NHEAD; h++) {
        e[h] = __expf(s[h] - m[h]);
        float v = e[h];
        #pragma unroll
        for (int o = 16; o; o >>= 1) v += __shfl_xor_sync(0xffffffffu, v, o);
        if (lane == 0) red[warp*NHEAD + h] = v;
    }
    __syncthreads();
    #pragma unroll
    for (int h = 0; h < NHEAD; h++) {
        float v = 0.f;
        #pragma unroll
        for (int w2 = 0; w2 < 8; w2++) v += red[w2*NHEAD + h];
        Zi[h] = 1.0f / v;
    }
    __syncthreads();

    // Store normalized weights transposed: w_sm[j][h]
    {
        float4 wlo = make_float4(e[0]*Zi[0], e[1]*Zi[1], e[2]*Zi[2], e[3]*Zi[3]);
        float4 whi = make_float4(e[4]*Zi[4], e[5]*Zi[5], e[6]*Zi[6], e[7]*Zi[7]);
        *(float4*)&w_sm[tid*8 + 0] = wlo;
        *(float4*)&w_sm[tid*8 + 4] = whi;
    }
    __syncthreads();

    // wp partials: thread = (c4, jgroup); all 8 heads in registers
    {
        const int c4 = tid & 15, jg = tid >> 4;
        float4 acc[NHEAD];
        #pragma unroll
        for (int h = 0; h < NHEAD; h++) acc[h] = make_float4(0.f,0.f,0.f,0.f);
        #pragma unroll 4
        for (int jj = 0; jj < 16; jj++) {
            int j = jg*16 + jj;
            float4 p  = *(const float4*)&pairS[j*PSTR + c4*4];
            float4 wA = *(const float4*)&w_sm[j*8];
            float4 wB = *(const float4*)&w_sm[j*8 + 4];
            acc[0].x += wA.x*p.x; acc[0].y += wA.x*p.y; acc[0].z += wA.x*p.z; acc[0].w += wA.x*p.w;
            acc[1].x += wA.y*p.x; acc[1].y += wA.y*p.y; acc[1].z += wA.y*p.z; acc[1].w += wA.y*p.w;
            acc[2].x += wA.z*p.x; acc[2].y += wA.z*p.y; acc[2].z += wA.z*p.z; acc[2].w += wA.z*p.w;
            acc[3].x += wA.w*p.x; acc[3].y += wA.w*p.y; acc[3].z += wA.w*p.z; acc[3].w += wA.w*p.w;
            acc[4].x += wB.x*p.x; acc[4].y += wB.x*p.y; acc[4].z += wB.x*p.z; acc[4].w += wB.x*p.w;
            acc[5].x += wB.y*p.x; acc[5].y += wB.y*p.y; acc[5].z += wB.y*p.z; acc[5].w += wB.y*p.w;
            acc[6].x += wB.z*p.x; acc[6].y += wB.z*p.y; acc[6].z += wB.z*p.z; acc[6].w += wB.z*p.w;
            acc[7].x += wB.w*p.x; acc[7].y += wB.w*p.y; acc[7].z += wB.w*p.z; acc[7].w += wB.w*p.w;
        }
        #pragma unroll
        for (int h = 0; h < NHEAD; h++)
            *(float4*)&red[((jg*NHEAD + h)*16 + c4)*4] = acc[h];
    }
    __syncthreads();

    // Final reduce over 16 jgroups -> g_wp
    if (tid < 128) {
        const int h = tid >> 4, c4 = tid & 15;
        float4 sum = make_float4(0.f,0.f,0.f,0.f);
        #pragma unroll
        for (int jg = 0; jg < 16; jg++) {
            float4 v = *(const float4*)&red[((jg*NHEAD + h)*16 + c4)*4];
            sum.x += v.x; sum.y += v.y; sum.z += v.z; sum.w += v.w;
        }
        *(float4*)&g_wp[row*DMODEL + h*64 + c4*4] = sum;
    }
}

// ---------------------------------------------------------------------------
// LayerNorm(sum_kz part + bvo + x) * gamma + beta -> out.
// ---------------------------------------------------------------------------
__global__ __launch_bounds__(128) void ln_kernel(
    const float* __restrict__ x, const float* __restrict__ gamma,
    const float* __restrict__ beta, float* __restrict__ out)
{
    __shared__ float rs[8];
    const int row = blockIdx.x;
    const int tid = threadIdx.x;
    const int lane = tid & 31, warp = tid >> 5;

    float4 x4 = *(const float4*)&x[row*DMODEL + tid*4];
    float4 b4v = *(const float4*)&g_bvo[tid*4];
    float y0 = x4.x + b4v.x, y1 = x4.y + b4v.y, y2 = x4.z + b4v.z, y3 = x4.w + b4v.w;
    #pragma unroll
    for (int kz = 0; kz < KSPLIT; kz++) {
        float4 p4 = *(const float4*)&g_part[((size_t)kz*NROWS + row)*DMODEL + tid*4];
        y0 += p4.x; y1 += p4.y; y2 += p4.z; y3 += p4.w;
    }

    float sum = y0 + y1 + y2 + y3;
    float sq  = y0*y0 + y1*y1 + y2*y2 + y3*y3;
    #pragma unroll
    for (int o = 16; o; o >>= 1) {
        sum += __shfl_xor_sync(0xffffffffu, sum, o);
        sq  += __shfl_xor_sync(0xffffffffu, sq,  o);
    }
    if (lane == 0) { rs[warp] = sum; rs[4 + warp] = sq; }
    __syncthreads();
    float ts = rs[0] + rs[1] + rs[2] + rs[3];
    float tq = rs[4] + rs[5] + rs[6] + rs[7];
    float mu  = ts * (1.0f/DMODEL);
    float var = tq * (1.0f/DMODEL) - mu*mu;
    float r = rsqrtf(var + 1e-5f);

    float4 g4 = *(const float4*)&gamma[tid*4];
    float4 b4 = *(const float4*)&beta[tid*4];
    float4 o_;
    o_.x = (y0 - mu)*r*g4.x + b4.x;
    o_.y = (y1 - mu)*r*g4.y + b4.y;
    o_.z = (y2 - mu)*r*g4.z + b4.z;
    o_.w = (y3 - mu)*r*g4.w + b4.w;
    *(float4*)&out[row*DMODEL + tid*4] = o_;
}

// ---------------------------------------------------------------------------
extern "C" void kernel_launch(void* const* d_in, const int* in_sizes, int n_in,
                              void* d_out, int out_size)
{
    const float* x     = (const float*)d_in[0];
    const float* pair  = (const float*)d_in[1];
    const float* Wq    = (const float*)d_in[2];
    const float* bq    = (const float*)d_in[3];
    const float* Wk    = (const float*)d_in[4];
    // bk (d_in[5]) is softmax-invariant (per-(row,h) constant), dropped
    const float* Wv    = (const float*)d_in[6];
    const float* bv    = (const float*)d_in[7];
    const float* Wo    = (const float*)d_in[8];
    const float* bo    = (const float*)d_in[9];
    const float* gamma = (const float*)d_in[10];
    const float* beta  = (const float*)d_in[11];
    float* out = (float*)d_out;

    float *pWP, *pWqk, *pWvo;
    cudaGetSymbolAddress((void**)&pWP,  g_wp);
    cudaGetSymbolAddress((void**)&pWqk, g_Wqk);
    cudaGetSymbolAddress((void**)&pWvo, g_Wvo);

    const int ATTN_SMEM = (256*PSTR + DMODEL + 2048 + 8192) * 4;  // 112640 B
    cudaFuncSetAttribute(attn_kernel, cudaFuncAttributeMaxDynamicSharedMemorySize, ATTN_SMEM);

    dim3 ggrid(DMODEL/64, NROWS/64, KSPLIT);   // (8,8,16) = 1024 blocks

    prep_kernel<<<136, 256>>>(Wq, bq, Wk, Wv, bv, Wo, bo);
    gemm_splitk_kernel<<<ggrid, 128>>>(x, pWqk);            // qk partials
    attn_kernel<<<NROWS, 256, ATTN_SMEM>>>(pair);           // reduce + softmax + wp
    gemm_splitk_kernel<<<ggrid, 128>>>(pWP, pWvo);          // o partials
    ln_kernel<<<NROWS, 128>>>(x, gamma, beta, out);         // reduce + LN(o + x)
}